// round 6
// baseline (speedup 1.0000x reference)
#include <cuda_runtime.h>
#include <cuda_bf16.h>

// ---------------------------------------------------------------------------
// CrossAttention: GroupNorm -> Qproj -> (LN -> KVproj) -> softmax(QK^T)V -> Oproj + residual
// Shapes: B=16, D=512, H=W=64 (HW=4096), S=256, CTX=768, G=32
// ---------------------------------------------------------------------------

constexpr int NB   = 16;
constexpr int ND   = 512;
constexpr int NHW  = 4096;
constexpr int NS   = 256;
constexpr int NCTX = 768;
constexpr int NG   = 32;
constexpr int NCPG = 16;     // channels per group
#define EPSV 1e-5f

// Scratch (allocation-free: device globals)
__device__ float g_sc[NB * ND];                    // per-(b,c) scale  = rstd*gamma
__device__ float g_sh[NB * ND];                    // per-(b,c) shift  = beta - mu*rstd*gamma
__device__ float g_cn[NB * NS * NCTX];             // LayerNormed context
__device__ float g_kv[NB * NS * 1024];             // [b][s][0:512]=k, [512:1024]=v
__device__ float g_q [NB * NHW * ND];              // [b][p][c]
__device__ float g_sim[NB * NHW * NS];             // [b][p][j]  (attn probs in-place)
__device__ float g_ao[NB * NHW * ND];              // [b][p][c]

// ---------------------------------------------------------------------------
// GroupNorm statistics -> fused scale/shift per (b, channel)
// grid: NB*NG blocks, 256 threads
// ---------------------------------------------------------------------------
__global__ void gn_stats_k(const float* __restrict__ x,
                           const float* __restrict__ gw,
                           const float* __restrict__ gb)
{
    int bg = blockIdx.x;            // b*NG + g
    int b = bg >> 5, g = bg & 31;
    const float4* p4 = (const float4*)(x + (size_t)bg * (NCPG * NHW));
    float s = 0.f, s2 = 0.f;
    const int n4 = NCPG * NHW / 4;  // 16384
    for (int i = threadIdx.x; i < n4; i += 256) {
        float4 v = p4[i];
        s  += v.x + v.y + v.z + v.w;
        s2 += v.x*v.x + v.y*v.y + v.z*v.z + v.w*v.w;
    }
    #pragma unroll
    for (int o = 16; o > 0; o >>= 1) {
        s  += __shfl_down_sync(0xffffffffu, s,  o);
        s2 += __shfl_down_sync(0xffffffffu, s2, o);
    }
    __shared__ float shs[8], shs2[8];
    int lane = threadIdx.x & 31, w = threadIdx.x >> 5;
    if (lane == 0) { shs[w] = s; shs2[w] = s2; }
    __syncthreads();
    __shared__ float mm, rr;
    if (threadIdx.x == 0) {
        float ts = 0.f, ts2 = 0.f;
        #pragma unroll
        for (int i = 0; i < 8; i++) { ts += shs[i]; ts2 += shs2[i]; }
        float inv_n = 1.f / (float)(NCPG * NHW);
        float mean = ts * inv_n;
        float var  = ts2 * inv_n - mean * mean;
        mm = mean;
        rr = rsqrtf(var + EPSV);
    }
    __syncthreads();
    if (threadIdx.x < NCPG) {
        int ch = g * NCPG + threadIdx.x;
        float wv = gw[ch], bv = gb[ch];
        g_sc[b * ND + ch] = rr * wv;
        g_sh[b * ND + ch] = bv - mm * rr * wv;
    }
}

// ---------------------------------------------------------------------------
// LayerNorm on context rows (NB*NS rows of NCTX), 256 threads/row
// ---------------------------------------------------------------------------
__global__ void ln_k(const float* __restrict__ ctx,
                     const float* __restrict__ lw,
                     const float* __restrict__ lb)
{
    int row = blockIdx.x;           // 0..NB*NS-1
    const float* p = ctx + (size_t)row * NCTX;
    float v[3];
    float s = 0.f, s2 = 0.f;
    #pragma unroll
    for (int r = 0; r < 3; r++) {
        v[r] = p[threadIdx.x + r * 256];
        s += v[r]; s2 += v[r] * v[r];
    }
    #pragma unroll
    for (int o = 16; o > 0; o >>= 1) {
        s  += __shfl_down_sync(0xffffffffu, s,  o);
        s2 += __shfl_down_sync(0xffffffffu, s2, o);
    }
    __shared__ float shs[8], shs2[8];
    int lane = threadIdx.x & 31, w = threadIdx.x >> 5;
    if (lane == 0) { shs[w] = s; shs2[w] = s2; }
    __syncthreads();
    __shared__ float mm, rr;
    if (threadIdx.x == 0) {
        float ts = 0.f, ts2 = 0.f;
        #pragma unroll
        for (int i = 0; i < 8; i++) { ts += shs[i]; ts2 += shs2[i]; }
        float inv_n = 1.f / (float)NCTX;
        float mean = ts * inv_n;
        float var  = ts2 * inv_n - mean * mean;
        mm = mean;
        rr = rsqrtf(var + EPSV);
    }
    __syncthreads();
    float* o = g_cn + (size_t)row * NCTX;
    #pragma unroll
    for (int r = 0; r < 3; r++) {
        int i = threadIdx.x + r * 256;
        o[i] = (v[r] - mm) * rr * lw[i] + lb[i];
    }
}

// ---------------------------------------------------------------------------
// Softmax over j (S=256) in-place on g_sim. One warp per row.
// grid: NB*NHW/8 blocks, 256 threads
// ---------------------------------------------------------------------------
__global__ void softmax_k()
{
    int row  = blockIdx.x * 8 + (threadIdx.x >> 5);
    int lane = threadIdx.x & 31;
    float* p = g_sim + (size_t)row * NS;
    float4 v0 = *(float4*)(p + lane * 4);
    float4 v1 = *(float4*)(p + 128 + lane * 4);
    float m = fmaxf(fmaxf(fmaxf(v0.x, v0.y), fmaxf(v0.z, v0.w)),
                    fmaxf(fmaxf(v1.x, v1.y), fmaxf(v1.z, v1.w)));
    #pragma unroll
    for (int o = 16; o > 0; o >>= 1) m = fmaxf(m, __shfl_xor_sync(0xffffffffu, m, o));
    v0.x = __expf(v0.x - m); v0.y = __expf(v0.y - m);
    v0.z = __expf(v0.z - m); v0.w = __expf(v0.w - m);
    v1.x = __expf(v1.x - m); v1.y = __expf(v1.y - m);
    v1.z = __expf(v1.z - m); v1.w = __expf(v1.w - m);
    float s = v0.x + v0.y + v0.z + v0.w + v1.x + v1.y + v1.z + v1.w;
    #pragma unroll
    for (int o = 16; o > 0; o >>= 1) s += __shfl_xor_sync(0xffffffffu, s, o);
    float inv = 1.f / s;
    v0.x *= inv; v0.y *= inv; v0.z *= inv; v0.w *= inv;
    v1.x *= inv; v1.y *= inv; v1.z *= inv; v1.w *= inv;
    *(float4*)(p + lane * 4) = v0;
    *(float4*)(p + 128 + lane * 4) = v1;
}

// ---------------------------------------------------------------------------
// Tiled SGEMM: C[M,N] = alpha * A(MxK) * B(KxN) (+bias[n]) per batch (grid.z).
// BM=BN=128, BK=16, 256 threads, 8x8 per thread. All dims divide tiles.
// AMODE 0: A[m*lda + k] (row-major)
// AMODE 1: A[k*lda + m] (x-layout), with per-k affine: a = a*sc[k] + shf[k]
// BMODE 0: B given as [n*ldb + k]  (i.e. B^T stored row-major over n)
// BMODE 1: B given as [k*ldb + n]
// EPI   0: C[m*ldc + n] = alpha*acc + bias[n]        (bias may be null)
// EPI   2: out[n*ldc + m] = acc + bias[n] + resid[n*ldc + m]  (transposed store)
// ---------------------------------------------------------------------------
template<int AMODE, int BMODE, int EPI>
__global__ __launch_bounds__(256, 2)
void gemm_k(const float* __restrict__ A, const float* __restrict__ Bm,
            float* __restrict__ Cp,
            const float* __restrict__ bias,
            const float* __restrict__ sc, const float* __restrict__ shf,
            const float* __restrict__ resid,
            float alpha, int K, int lda, int ldb, int ldc,
            long sA, long sB, long sC)
{
    __shared__ float As[16][132];
    __shared__ float Bs[16][132];

    const int tid = threadIdx.x;
    const int bz  = blockIdx.z;
    A  += (size_t)bz * sA;
    Bm += (size_t)bz * sB;
    const int m0 = blockIdx.x * 128;
    const int n0 = blockIdx.y * 128;

    float acc[8][8];
    #pragma unroll
    for (int i = 0; i < 8; i++)
        #pragma unroll
        for (int j = 0; j < 8; j++) acc[i][j] = 0.f;

    const int tx = tid & 15;   // n
    const int ty = tid >> 4;   // m

    for (int k0 = 0; k0 < K; k0 += 16) {
        // ---- load A tile ----
        if (AMODE == 0) {
            int tM = tid >> 2, tK = (tid & 3) * 4;
            #pragma unroll
            for (int r = 0; r < 2; r++) {
                int m = m0 + tM + r * 64;
                float4 v = *(const float4*)(A + (size_t)m * lda + k0 + tK);
                As[tK + 0][tM + r * 64] = v.x;
                As[tK + 1][tM + r * 64] = v.y;
                As[tK + 2][tM + r * 64] = v.z;
                As[tK + 3][tM + r * 64] = v.w;
            }
        } else {
            int tK = tid >> 5, tM = (tid & 31) * 4;
            #pragma unroll
            for (int r = 0; r < 2; r++) {
                int k = k0 + tK + r * 8;
                float4 v = *(const float4*)(A + (size_t)k * lda + m0 + tM);
                float s = sc[(size_t)bz * ND + k];
                float t = shf[(size_t)bz * ND + k];
                v.x = v.x * s + t; v.y = v.y * s + t;
                v.z = v.z * s + t; v.w = v.w * s + t;
                *(float4*)&As[tK + r * 8][tM] = v;
            }
        }
        // ---- load B tile ----
        if (BMODE == 0) {
            int tN = tid >> 2, tK = (tid & 3) * 4;
            #pragma unroll
            for (int r = 0; r < 2; r++) {
                int n = n0 + tN + r * 64;
                float4 v = *(const float4*)(Bm + (size_t)n * ldb + k0 + tK);
                Bs[tK + 0][tN + r * 64] = v.x;
                Bs[tK + 1][tN + r * 64] = v.y;
                Bs[tK + 2][tN + r * 64] = v.z;
                Bs[tK + 3][tN + r * 64] = v.w;
            }
        } else {
            int tK = tid >> 5, tN = (tid & 31) * 4;
            #pragma unroll
            for (int r = 0; r < 2; r++) {
                int k = tK + r * 8;
                float4 v = *(const float4*)(Bm + (size_t)(k0 + k) * ldb + n0 + tN);
                *(float4*)&Bs[k][tN] = v;
            }
        }
        __syncthreads();

        #pragma unroll
        for (int kk = 0; kk < 16; kk++) {
            float a[8], bb[8];
            *(float4*)&a[0]  = *(const float4*)&As[kk][ty * 8];
            *(float4*)&a[4]  = *(const float4*)&As[kk][ty * 8 + 4];
            *(float4*)&bb[0] = *(const float4*)&Bs[kk][tx * 8];
            *(float4*)&bb[4] = *(const float4*)&Bs[kk][tx * 8 + 4];
            #pragma unroll
            for (int i = 0; i < 8; i++)
                #pragma unroll
                for (int j = 0; j < 8; j++)
                    acc[i][j] += a[i] * bb[j];
        }
        __syncthreads();
    }

    Cp += (size_t)bz * sC;
    if (EPI == 0) {
        #pragma unroll
        for (int i = 0; i < 8; i++) {
            size_t rbase = (size_t)(m0 + ty * 8 + i) * ldc;
            #pragma unroll
            for (int j2 = 0; j2 < 2; j2++) {
                int n = n0 + tx * 8 + j2 * 4;
                float4 o;
                o.x = alpha * acc[i][j2 * 4 + 0];
                o.y = alpha * acc[i][j2 * 4 + 1];
                o.z = alpha * acc[i][j2 * 4 + 2];
                o.w = alpha * acc[i][j2 * 4 + 3];
                if (bias) {
                    o.x += bias[n + 0]; o.y += bias[n + 1];
                    o.z += bias[n + 2]; o.w += bias[n + 3];
                }
                *(float4*)(Cp + rbase + n) = o;
            }
        }
    } else { // EPI == 2 : transposed store with bias + residual
        const float* R = resid + (size_t)bz * sC;
        #pragma unroll
        for (int j = 0; j < 8; j++) {
            int n = n0 + tx * 8 + j;
            float bv = bias[n];
            #pragma unroll
            for (int i2 = 0; i2 < 2; i2++) {
                size_t off = (size_t)n * ldc + m0 + ty * 8 + i2 * 4;
                float4 rv = *(const float4*)(R + off);
                float4 o;
                o.x = acc[i2 * 4 + 0][j] + bv + rv.x;
                o.y = acc[i2 * 4 + 1][j] + bv + rv.y;
                o.z = acc[i2 * 4 + 2][j] + bv + rv.z;
                o.w = acc[i2 * 4 + 3][j] + bv + rv.w;
                *(float4*)(Cp + off) = o;
            }
        }
    }
}

// ---------------------------------------------------------------------------
extern "C" void kernel_launch(void* const* d_in, const int* in_sizes, int n_in,
                              void* d_out, int out_size)
{
    const float* x    = (const float*)d_in[0];
    const float* ctx  = (const float*)d_in[1];
    const float* gn_w = (const float*)d_in[2];
    const float* gn_b = (const float*)d_in[3];
    const float* ln_w = (const float*)d_in[4];
    const float* ln_b = (const float*)d_in[5];
    const float* wq   = (const float*)d_in[6];
    const float* bq   = (const float*)d_in[7];
    const float* wkv  = (const float*)d_in[8];
    const float* bkv  = (const float*)d_in[9];
    const float* wo   = (const float*)d_in[10];
    const float* bo   = (const float*)d_in[11];
    float* out = (float*)d_out;

    float *p_cn, *p_kv, *p_q, *p_sim, *p_ao;
    cudaGetSymbolAddress((void**)&p_cn,  g_cn);
    cudaGetSymbolAddress((void**)&p_kv,  g_kv);
    cudaGetSymbolAddress((void**)&p_q,   g_q);
    cudaGetSymbolAddress((void**)&p_sim, g_sim);
    cudaGetSymbolAddress((void**)&p_ao,  g_ao);
    float *p_sc, *p_sh;
    cudaGetSymbolAddress((void**)&p_sc, g_sc);
    cudaGetSymbolAddress((void**)&p_sh, g_sh);

    // 1) GroupNorm stats -> fused scale/shift
    gn_stats_k<<<NB * NG, 256>>>(x, gn_w, gn_b);

    // 2) LayerNorm on context
    ln_k<<<NB * NS, 256>>>(ctx, ln_w, ln_b);

    // 3) KV projection: [S,1024] = cn[S,768] @ wkv^T + bkv
    gemm_k<0, 0, 0><<<dim3(NS / 128, 1024 / 128, NB), 256>>>(
        p_cn, wkv, p_kv, bkv, nullptr, nullptr, nullptr,
        1.f, NCTX, NCTX, NCTX, 1024,
        (long)NS * NCTX, 0L, (long)NS * 1024);

    // 4) Q projection (GroupNorm fused into A load): q[p,o] = xn[p,c] @ wq^T + bq
    gemm_k<1, 0, 0><<<dim3(NHW / 128, ND / 128, NB), 256>>>(
        x, wq, p_q, bq, p_sc, p_sh, nullptr,
        1.f, ND, NHW, ND, ND,
        (long)ND * NHW, 0L, (long)NHW * ND);

    // 5) sim[p,j] = scale * q[p,c] @ k[j,c]^T
    gemm_k<0, 0, 0><<<dim3(NHW / 128, NS / 128, NB), 256>>>(
        p_q, p_kv, p_sim, nullptr, nullptr, nullptr, nullptr,
        0.044194173824159216f /* 512^-0.5 */, ND, ND, 1024, NS,
        (long)NHW * ND, (long)NS * 1024, (long)NHW * NS);

    // 6) softmax over j (in place)
    softmax_k<<<NB * NHW / 8, 256>>>();

    // 7) ao[p,c] = P[p,j] @ v[j,c]
    gemm_k<0, 1, 0><<<dim3(NHW / 128, ND / 128, NB), 256>>>(
        p_sim, p_kv + 512, p_ao, nullptr, nullptr, nullptr, nullptr,
        1.f, NS, NS, 1024, ND,
        (long)NHW * NS, (long)NS * 1024, (long)NHW * ND);

    // 8) O projection + bias + residual, transposed store to [b,c,hw]
    gemm_k<0, 0, 2><<<dim3(NHW / 128, ND / 128, NB), 256>>>(
        p_ao, wo, out, bo, nullptr, nullptr, x,
        1.f, ND, ND, ND, NHW,
        (long)NHW * ND, 0L, (long)ND * NHW);
}

// round 7
// speedup vs baseline: 1.9607x; 1.9607x over previous
#include <cuda_runtime.h>
#include <cuda_bf16.h>
#include <cstdint>

// ---------------------------------------------------------------------------
// CrossAttention: GroupNorm -> Qproj -> (LN -> KVproj) -> softmax(QK^T)V -> Oproj + residual
// B=16, D=512, HW=4096, S=256, CTX=768, G=32
// GEMMs run on tensor cores via mma.m16n8k16.bf16 with split-bf16 (3-product)
// for ~fp32 accuracy.
// ---------------------------------------------------------------------------

constexpr int NB   = 16;
constexpr int ND   = 512;
constexpr int NHW  = 4096;
constexpr int NS   = 256;
constexpr int NCTX = 768;
constexpr int NCPG = 16;     // channels per group (32 groups)
#define EPSV 1e-5f

// Scratch (allocation-free: device globals)
__device__ float g_sc[NB * ND];                    // per-(b,c) scale  = rstd*gamma
__device__ float g_sh[NB * ND];                    // per-(b,c) shift  = beta - mu*rstd*gamma
__device__ float g_cn[NB * NS * NCTX];             // LayerNormed context
__device__ float g_kv[NB * NS * 1024];             // [b][s][0:512]=k, [512:1024]=v
__device__ float g_q [NB * NHW * ND];              // [b][p][c]
__device__ float g_sim[(size_t)NB * NHW * NS];     // [b][p][j]  (probs in-place)
__device__ float g_ao[(size_t)NB * NHW * ND];      // [b][p][c]

// ---------------------------------------------------------------------------
// GroupNorm statistics -> fused scale/shift per (b, channel)
// ---------------------------------------------------------------------------
__global__ void gn_stats_k(const float* __restrict__ x,
                           const float* __restrict__ gw,
                           const float* __restrict__ gb)
{
    int bg = blockIdx.x;            // b*32 + g
    int b = bg >> 5, g = bg & 31;
    const float4* p4 = (const float4*)(x + (size_t)bg * (NCPG * NHW));
    float s = 0.f, s2 = 0.f;
    const int n4 = NCPG * NHW / 4;
    for (int i = threadIdx.x; i < n4; i += 256) {
        float4 v = p4[i];
        s  += v.x + v.y + v.z + v.w;
        s2 += v.x*v.x + v.y*v.y + v.z*v.z + v.w*v.w;
    }
    #pragma unroll
    for (int o = 16; o > 0; o >>= 1) {
        s  += __shfl_down_sync(0xffffffffu, s,  o);
        s2 += __shfl_down_sync(0xffffffffu, s2, o);
    }
    __shared__ float shs[8], shs2[8];
    int lane = threadIdx.x & 31, w = threadIdx.x >> 5;
    if (lane == 0) { shs[w] = s; shs2[w] = s2; }
    __syncthreads();
    __shared__ float mm, rr;
    if (threadIdx.x == 0) {
        float ts = 0.f, ts2 = 0.f;
        #pragma unroll
        for (int i = 0; i < 8; i++) { ts += shs[i]; ts2 += shs2[i]; }
        float inv_n = 1.f / (float)(NCPG * NHW);
        float mean = ts * inv_n;
        float var  = ts2 * inv_n - mean * mean;
        mm = mean;
        rr = rsqrtf(var + EPSV);
    }
    __syncthreads();
    if (threadIdx.x < NCPG) {
        int ch = g * NCPG + threadIdx.x;
        float wv = gw[ch], bv = gb[ch];
        g_sc[b * ND + ch] = rr * wv;
        g_sh[b * ND + ch] = bv - mm * rr * wv;
    }
}

// ---------------------------------------------------------------------------
// LayerNorm on context rows
// ---------------------------------------------------------------------------
__global__ void ln_k(const float* __restrict__ ctx,
                     const float* __restrict__ lw,
                     const float* __restrict__ lb)
{
    int row = blockIdx.x;
    const float* p = ctx + (size_t)row * NCTX;
    float v[3];
    float s = 0.f, s2 = 0.f;
    #pragma unroll
    for (int r = 0; r < 3; r++) {
        v[r] = p[threadIdx.x + r * 256];
        s += v[r]; s2 += v[r] * v[r];
    }
    #pragma unroll
    for (int o = 16; o > 0; o >>= 1) {
        s  += __shfl_down_sync(0xffffffffu, s,  o);
        s2 += __shfl_down_sync(0xffffffffu, s2, o);
    }
    __shared__ float shs[8], shs2[8];
    int lane = threadIdx.x & 31, w = threadIdx.x >> 5;
    if (lane == 0) { shs[w] = s; shs2[w] = s2; }
    __syncthreads();
    __shared__ float mm, rr;
    if (threadIdx.x == 0) {
        float ts = 0.f, ts2 = 0.f;
        #pragma unroll
        for (int i = 0; i < 8; i++) { ts += shs[i]; ts2 += shs2[i]; }
        float inv_n = 1.f / (float)NCTX;
        float mean = ts * inv_n;
        float var  = ts2 * inv_n - mean * mean;
        mm = mean;
        rr = rsqrtf(var + EPSV);
    }
    __syncthreads();
    float* o = g_cn + (size_t)row * NCTX;
    #pragma unroll
    for (int r = 0; r < 3; r++) {
        int i = threadIdx.x + r * 256;
        o[i] = (v[r] - mm) * rr * lw[i] + lb[i];
    }
}

// ---------------------------------------------------------------------------
// Softmax over j (S=256) in-place on g_sim. One warp per row.
// ---------------------------------------------------------------------------
__global__ void softmax_k()
{
    size_t row = (size_t)blockIdx.x * 8 + (threadIdx.x >> 5);
    int lane = threadIdx.x & 31;
    float* p = g_sim + row * NS;
    float4 v0 = *(float4*)(p + lane * 4);
    float4 v1 = *(float4*)(p + 128 + lane * 4);
    float m = fmaxf(fmaxf(fmaxf(v0.x, v0.y), fmaxf(v0.z, v0.w)),
                    fmaxf(fmaxf(v1.x, v1.y), fmaxf(v1.z, v1.w)));
    #pragma unroll
    for (int o = 16; o > 0; o >>= 1) m = fmaxf(m, __shfl_xor_sync(0xffffffffu, m, o));
    v0.x = __expf(v0.x - m); v0.y = __expf(v0.y - m);
    v0.z = __expf(v0.z - m); v0.w = __expf(v0.w - m);
    v1.x = __expf(v1.x - m); v1.y = __expf(v1.y - m);
    v1.z = __expf(v1.z - m); v1.w = __expf(v1.w - m);
    float s = v0.x + v0.y + v0.z + v0.w + v1.x + v1.y + v1.z + v1.w;
    #pragma unroll
    for (int o = 16; o > 0; o >>= 1) s += __shfl_xor_sync(0xffffffffu, s, o);
    float inv = 1.f / s;
    v0.x *= inv; v0.y *= inv; v0.z *= inv; v0.w *= inv;
    v1.x *= inv; v1.y *= inv; v1.z *= inv; v1.w *= inv;
    *(float4*)(p + lane * 4) = v0;
    *(float4*)(p + 128 + lane * 4) = v1;
}

// ---------------------------------------------------------------------------
// Split-bf16 helpers
// ---------------------------------------------------------------------------
__device__ __forceinline__ void pack2(float v0, float v1, uint32_t& hp, uint32_t& lp)
{
    __nv_bfloat16 h0 = __float2bfloat16(v0);
    __nv_bfloat16 h1 = __float2bfloat16(v1);
    float r0 = v0 - __bfloat162float(h0);
    float r1 = v1 - __bfloat162float(h1);
    __nv_bfloat16 l0 = __float2bfloat16(r0);
    __nv_bfloat16 l1 = __float2bfloat16(r1);
    hp = (uint32_t)__bfloat16_as_ushort(h0) | ((uint32_t)__bfloat16_as_ushort(h1) << 16);
    lp = (uint32_t)__bfloat16_as_ushort(l0) | ((uint32_t)__bfloat16_as_ushort(l1) << 16);
}

__device__ __forceinline__ void mma16816(float* d, const uint32_t* a, const uint32_t* b)
{
    asm volatile(
        "mma.sync.aligned.m16n8k16.row.col.f32.bf16.bf16.f32 "
        "{%0,%1,%2,%3},{%4,%5,%6,%7},{%8,%9},{%0,%1,%2,%3};"
        : "+f"(d[0]), "+f"(d[1]), "+f"(d[2]), "+f"(d[3])
        : "r"(a[0]), "r"(a[1]), "r"(a[2]), "r"(a[3]), "r"(b[0]), "r"(b[1]));
}

// ---------------------------------------------------------------------------
// Tensor-core GEMM: C[M,N] = alpha * A(MxK) * B(KxN), split-bf16 (3 products).
// Block 128x128, BK=16, 256 threads (8 warps, warp tile 64x32), double-buffered.
// AMODE 0: A[m*lda + k]                (k contiguous)
// AMODE 1: A[k*lda + m], affine a = a*sc[k]+shf[k] (GroupNorm fusion; k-dim=512)
// BMODE 0: B given as [n*ldb + k]      (k contiguous)
// BMODE 1: B given as [k*ldb + n]
// EPI   0: C[m*ldc + n] = alpha*acc + bias_n[n]       (bias may be null)
// EPI   3: C[m*ldc + n] = acc + bias_m[m] + resid[m*ldc + n]
// ---------------------------------------------------------------------------
template<int AMODE, int BMODE, int EPI>
__global__ __launch_bounds__(256, 2)
void gemm_k(const float* __restrict__ A, const float* __restrict__ Bm,
            float* __restrict__ Cp, const float* __restrict__ bias,
            const float* __restrict__ sc, const float* __restrict__ shf,
            const float* __restrict__ resid,
            float alpha, int K, int lda, int ldb, int ldc,
            long sA, long sB, long sC)
{
    // hi/lo bf16 planes, 128 rows x 12 words (16 bf16 + pad), double buffered
    __shared__ uint32_t AsH[2][128 * 12];
    __shared__ uint32_t AsL[2][128 * 12];
    __shared__ uint32_t BsH[2][128 * 12];
    __shared__ uint32_t BsL[2][128 * 12];

    const int tid  = threadIdx.x;
    const int lane = tid & 31, wid = tid >> 5;
    const int bz   = blockIdx.z;
    const float* Ap = A  + (size_t)bz * sA;
    const float* Bp = Bm + (size_t)bz * sB;
    const int m0 = blockIdx.x * 128;
    const int n0 = blockIdx.y * 128;

    float rA[8], rB[8];

    auto loadA = [&](int k0) {
        if constexpr (AMODE == 0) {
            int tM = tid >> 2, tK = (tid & 3) * 4;
            *(float4*)&rA[0] = *(const float4*)(Ap + (size_t)(m0 + tM)      * lda + k0 + tK);
            *(float4*)&rA[4] = *(const float4*)(Ap + (size_t)(m0 + tM + 64) * lda + k0 + tK);
        } else {
            int tM = tid & 127, tK = (tid >> 7) * 4;
            #pragma unroll
            for (int kr = 0; kr < 2; kr++) {
                #pragma unroll
                for (int i = 0; i < 4; i++) {
                    int k = k0 + tK + 8 * kr + i;
                    float v = Ap[(size_t)k * lda + m0 + tM];
                    float s = sc [bz * ND + k];
                    float t = shf[bz * ND + k];
                    rA[4 * kr + i] = v * s + t;
                }
            }
        }
    };
    auto stsA = [&](int buf) {
        if constexpr (AMODE == 0) {
            int tM = tid >> 2, tKw = (tid & 3) * 2;
            #pragma unroll
            for (int r = 0; r < 2; r++) {
                uint32_t h0, l0, h1, l1;
                pack2(rA[4*r + 0], rA[4*r + 1], h0, l0);
                pack2(rA[4*r + 2], rA[4*r + 3], h1, l1);
                int off = (tM + 64 * r) * 12 + tKw;
                *(uint2*)&AsH[buf][off] = make_uint2(h0, h1);
                *(uint2*)&AsL[buf][off] = make_uint2(l0, l1);
            }
        } else {
            int tM = tid & 127, tKw = (tid >> 7) * 2;
            #pragma unroll
            for (int kr = 0; kr < 2; kr++) {
                uint32_t h0, l0, h1, l1;
                pack2(rA[4*kr + 0], rA[4*kr + 1], h0, l0);
                pack2(rA[4*kr + 2], rA[4*kr + 3], h1, l1);
                int off = tM * 12 + tKw + 4 * kr;
                *(uint2*)&AsH[buf][off] = make_uint2(h0, h1);
                *(uint2*)&AsL[buf][off] = make_uint2(l0, l1);
            }
        }
    };
    auto loadB = [&](int k0) {
        if constexpr (BMODE == 0) {
            int tN = tid >> 2, tK = (tid & 3) * 4;
            *(float4*)&rB[0] = *(const float4*)(Bp + (size_t)(n0 + tN)      * ldb + k0 + tK);
            *(float4*)&rB[4] = *(const float4*)(Bp + (size_t)(n0 + tN + 64) * ldb + k0 + tK);
        } else {
            int tN = tid & 127, tK = (tid >> 7) * 4;
            #pragma unroll
            for (int kr = 0; kr < 2; kr++) {
                #pragma unroll
                for (int i = 0; i < 4; i++) {
                    int k = k0 + tK + 8 * kr + i;
                    rB[4 * kr + i] = Bp[(size_t)k * ldb + n0 + tN];
                }
            }
        }
    };
    auto stsB = [&](int buf) {
        if constexpr (BMODE == 0) {
            int tN = tid >> 2, tKw = (tid & 3) * 2;
            #pragma unroll
            for (int r = 0; r < 2; r++) {
                uint32_t h0, l0, h1, l1;
                pack2(rB[4*r + 0], rB[4*r + 1], h0, l0);
                pack2(rB[4*r + 2], rB[4*r + 3], h1, l1);
                int off = (tN + 64 * r) * 12 + tKw;
                *(uint2*)&BsH[buf][off] = make_uint2(h0, h1);
                *(uint2*)&BsL[buf][off] = make_uint2(l0, l1);
            }
        } else {
            int tN = tid & 127, tKw = (tid >> 7) * 2;
            #pragma unroll
            for (int kr = 0; kr < 2; kr++) {
                uint32_t h0, l0, h1, l1;
                pack2(rB[4*kr + 0], rB[4*kr + 1], h0, l0);
                pack2(rB[4*kr + 2], rB[4*kr + 3], h1, l1);
                int off = tN * 12 + tKw + 4 * kr;
                *(uint2*)&BsH[buf][off] = make_uint2(h0, h1);
                *(uint2*)&BsL[buf][off] = make_uint2(l0, l1);
            }
        }
    };

    const int g  = lane >> 2, tg = lane & 3;
    const int mw = (wid & 1) * 64, nw = (wid >> 1) * 32;

    float acc[4][4][4];
    #pragma unroll
    for (int i = 0; i < 4; i++)
        #pragma unroll
        for (int j = 0; j < 4; j++)
            #pragma unroll
            for (int q = 0; q < 4; q++) acc[i][j][q] = 0.f;

    const int nIter = K >> 4;
    loadA(0); loadB(0);
    stsA(0);  stsB(0);
    __syncthreads();

    for (int it = 0; it < nIter; it++) {
        const int cur = it & 1;
        if (it + 1 < nIter) { loadA((it + 1) << 4); loadB((it + 1) << 4); }

        const uint32_t* aH = AsH[cur];
        const uint32_t* aL = AsL[cur];
        const uint32_t* bH = BsH[cur];
        const uint32_t* bL = BsL[cur];

        uint32_t ah[4][4], bh[4][2], bl[4][2];
        #pragma unroll
        for (int i = 0; i < 4; i++) {
            int mr = mw + 16 * i + g;
            ah[i][0] = aH[mr * 12 + tg];
            ah[i][1] = aH[(mr + 8) * 12 + tg];
            ah[i][2] = aH[mr * 12 + tg + 4];
            ah[i][3] = aH[(mr + 8) * 12 + tg + 4];
        }
        #pragma unroll
        for (int j = 0; j < 4; j++) {
            int nr = nw + 8 * j + g;
            bh[j][0] = bH[nr * 12 + tg];
            bh[j][1] = bH[nr * 12 + tg + 4];
            bl[j][0] = bL[nr * 12 + tg];
            bl[j][1] = bL[nr * 12 + tg + 4];
        }
        #pragma unroll
        for (int i = 0; i < 4; i++)
            #pragma unroll
            for (int j = 0; j < 4; j++)
                mma16816(acc[i][j], ah[i], bh[j]);
        #pragma unroll
        for (int i = 0; i < 4; i++)
            #pragma unroll
            for (int j = 0; j < 4; j++)
                mma16816(acc[i][j], ah[i], bl[j]);
        // lo(A) x hi(B): reload A frags from lo plane (reuses ah registers)
        #pragma unroll
        for (int i = 0; i < 4; i++) {
            int mr = mw + 16 * i + g;
            ah[i][0] = aL[mr * 12 + tg];
            ah[i][1] = aL[(mr + 8) * 12 + tg];
            ah[i][2] = aL[mr * 12 + tg + 4];
            ah[i][3] = aL[(mr + 8) * 12 + tg + 4];
        }
        #pragma unroll
        for (int i = 0; i < 4; i++)
            #pragma unroll
            for (int j = 0; j < 4; j++)
                mma16816(acc[i][j], ah[i], bh[j]);

        if (it + 1 < nIter) {
            stsA((it + 1) & 1); stsB((it + 1) & 1);
            __syncthreads();
        }
    }

    float* Co = Cp + (size_t)bz * sC;
    if constexpr (EPI == 0) {
        #pragma unroll
        for (int i = 0; i < 4; i++) {
            int r = m0 + mw + 16 * i + g;
            #pragma unroll
            for (int j = 0; j < 4; j++) {
                int c = n0 + nw + 8 * j + 2 * tg;
                float b0v = 0.f, b1v = 0.f;
                if (bias) { b0v = bias[c]; b1v = bias[c + 1]; }
                float2 v0 = make_float2(alpha * acc[i][j][0] + b0v,
                                        alpha * acc[i][j][1] + b1v);
                float2 v1 = make_float2(alpha * acc[i][j][2] + b0v,
                                        alpha * acc[i][j][3] + b1v);
                *(float2*)(Co + (size_t)r * ldc + c)       = v0;
                *(float2*)(Co + (size_t)(r + 8) * ldc + c) = v1;
            }
        }
    } else { // EPI == 3: bias by row + residual add, C row-major [m][n]
        const float* R = resid + (size_t)bz * sC;
        #pragma unroll
        for (int i = 0; i < 4; i++) {
            int r = m0 + mw + 16 * i + g;
            float bv0 = bias[r], bv1 = bias[r + 8];
            #pragma unroll
            for (int j = 0; j < 4; j++) {
                int c = n0 + nw + 8 * j + 2 * tg;
                float2 rv0 = *(const float2*)(R + (size_t)r * ldc + c);
                float2 rv1 = *(const float2*)(R + (size_t)(r + 8) * ldc + c);
                float2 v0 = make_float2(acc[i][j][0] + bv0 + rv0.x,
                                        acc[i][j][1] + bv0 + rv0.y);
                float2 v1 = make_float2(acc[i][j][2] + bv1 + rv1.x,
                                        acc[i][j][3] + bv1 + rv1.y);
                *(float2*)(Co + (size_t)r * ldc + c)       = v0;
                *(float2*)(Co + (size_t)(r + 8) * ldc + c) = v1;
            }
        }
    }
}

// ---------------------------------------------------------------------------
extern "C" void kernel_launch(void* const* d_in, const int* in_sizes, int n_in,
                              void* d_out, int out_size)
{
    const float* x    = (const float*)d_in[0];
    const float* ctx  = (const float*)d_in[1];
    const float* gn_w = (const float*)d_in[2];
    const float* gn_b = (const float*)d_in[3];
    const float* ln_w = (const float*)d_in[4];
    const float* ln_b = (const float*)d_in[5];
    const float* wq   = (const float*)d_in[6];
    const float* bq   = (const float*)d_in[7];
    const float* wkv  = (const float*)d_in[8];
    const float* bkv  = (const float*)d_in[9];
    const float* wo   = (const float*)d_in[10];
    const float* bo   = (const float*)d_in[11];
    float* out = (float*)d_out;

    float *p_cn, *p_kv, *p_q, *p_sim, *p_ao, *p_sc, *p_sh;
    cudaGetSymbolAddress((void**)&p_cn,  g_cn);
    cudaGetSymbolAddress((void**)&p_kv,  g_kv);
    cudaGetSymbolAddress((void**)&p_q,   g_q);
    cudaGetSymbolAddress((void**)&p_sim, g_sim);
    cudaGetSymbolAddress((void**)&p_ao,  g_ao);
    cudaGetSymbolAddress((void**)&p_sc,  g_sc);
    cudaGetSymbolAddress((void**)&p_sh,  g_sh);

    // 1) GroupNorm stats -> fused scale/shift
    gn_stats_k<<<NB * 32, 256>>>(x, gn_w, gn_b);

    // 2) LayerNorm on context
    ln_k<<<NB * NS, 256>>>(ctx, ln_w, ln_b);

    // 3) KV projection: kv[S,1024] = cn[S,768] @ wkv^T + bkv
    gemm_k<0, 0, 0><<<dim3(NS / 128, 1024 / 128, NB), 256>>>(
        p_cn, wkv, p_kv, bkv, nullptr, nullptr, nullptr,
        1.f, NCTX, NCTX, NCTX, 1024,
        (long)NS * NCTX, 0L, (long)NS * 1024);

    // 4) Q projection (GroupNorm fused into A load): q[p,o] = xn[p,c] @ wq^T + bq
    gemm_k<1, 0, 0><<<dim3(NHW / 128, ND / 128, NB), 256>>>(
        x, wq, p_q, bq, p_sc, p_sh, nullptr,
        1.f, ND, NHW, ND, ND,
        (long)ND * NHW, 0L, (long)NHW * ND);

    // 5) sim[p,j] = scale * q[p,c] @ k[j,c]^T
    gemm_k<0, 0, 0><<<dim3(NHW / 128, NS / 128, NB), 256>>>(
        p_q, p_kv, p_sim, nullptr, nullptr, nullptr, nullptr,
        0.044194173824159216f /* 512^-0.5 */, ND, ND, 1024, NS,
        (long)NHW * ND, (long)NS * 1024, (long)NHW * NS);

    // 6) softmax over j (in place)
    softmax_k<<<NB * NHW / 8, 256>>>();

    // 7) ao[p,c] = P[p,j] @ v[j,c]   (V is [s][c] -> BMODE1)
    gemm_k<0, 1, 0><<<dim3(NHW / 128, ND / 128, NB), 256>>>(
        p_sim, p_kv + 512, p_ao, nullptr, nullptr, nullptr, nullptr,
        1.f, NS, NS, 1024, ND,
        (long)NHW * NS, (long)NS * 1024, (long)NHW * ND);

    // 8) O projection, computed transposed: out[c,p] = wo[c,c'] @ ao[p,c']^T
    //    + bo[c] + x[c,p]  -> coalesced [b,c,hw] store with fused residual
    gemm_k<0, 0, 3><<<dim3(ND / 128, NHW / 128, NB), 256>>>(
        wo, p_ao, out, bo, nullptr, nullptr, x,
        1.f, ND, ND, ND, NHW,
        0L, (long)NHW * ND, (long)ND * NHW);
}

// round 8
// speedup vs baseline: 1.9717x; 1.0056x over previous
#include <cuda_runtime.h>
#include <cuda_bf16.h>
#include <cstdint>

// ---------------------------------------------------------------------------
// CrossAttention, all-bf16 split dataflow:
// GN-> (x hi/lo planes) -> Qproj -> sim -> softmax -> PV -> Oproj(+res)
// LN-> (cn hi/lo)       -> Kproj/Vproj
// GEMMs: mma.m16n8k16.bf16, 3-product split (AhBh + AhBl + AlBh) ~ fp32.
// cp.async 3-stage pipeline + ldmatrix fragments.
// ---------------------------------------------------------------------------

constexpr int NB   = 16;
constexpr int ND   = 512;
constexpr int NHW  = 4096;
constexpr int NS   = 256;
constexpr int NCTX = 768;
constexpr int NCPG = 16;
#define EPSV 1e-5f

typedef __nv_bfloat16 bf16;

// ---- scratch (device globals; allocation-free) ----
__device__ float g_sc[NB * ND];
__device__ float g_sh[NB * ND];
__device__ bf16 g_xnh[(size_t)NB * NHW * ND], g_xnl[(size_t)NB * NHW * ND];
__device__ bf16 g_qh [(size_t)NB * NHW * ND], g_ql [(size_t)NB * NHW * ND];
__device__ bf16 g_aoh[(size_t)NB * NHW * ND], g_aol[(size_t)NB * NHW * ND];
__device__ bf16 g_Ph [(size_t)NB * NHW * NS], g_Pl [(size_t)NB * NHW * NS];
__device__ float g_sim[(size_t)NB * NHW * NS];
__device__ bf16 g_cnh[NB * NS * NCTX], g_cnl[NB * NS * NCTX];
__device__ bf16 g_kh [NB * NS * ND],   g_kl [NB * NS * ND];
__device__ bf16 g_vh [NB * ND * NS],   g_vl [NB * ND * NS];
__device__ bf16 g_wqh [ND * ND],     g_wql [ND * ND];
__device__ bf16 g_wkvh[1024 * NCTX], g_wkvl[1024 * NCTX];
__device__ bf16 g_woh [ND * ND],     g_wol [ND * ND];

// ---------------------------------------------------------------------------
__device__ __forceinline__ void split1(float v, bf16& h, bf16& l)
{
    h = __float2bfloat16(v);
    l = __float2bfloat16(v - __bfloat162float(h));
}

// ---------------------------------------------------------------------------
// GroupNorm statistics -> per-(b,c) scale/shift
// ---------------------------------------------------------------------------
__global__ void gn_stats_k(const float* __restrict__ x,
                           const float* __restrict__ gw,
                           const float* __restrict__ gb)
{
    int bg = blockIdx.x;
    int b = bg >> 5, g = bg & 31;
    const float4* p4 = (const float4*)(x + (size_t)bg * (NCPG * NHW));
    float s = 0.f, s2 = 0.f;
    const int n4 = NCPG * NHW / 4;
    for (int i = threadIdx.x; i < n4; i += 256) {
        float4 v = p4[i];
        s  += v.x + v.y + v.z + v.w;
        s2 += v.x*v.x + v.y*v.y + v.z*v.z + v.w*v.w;
    }
    #pragma unroll
    for (int o = 16; o > 0; o >>= 1) {
        s  += __shfl_down_sync(0xffffffffu, s,  o);
        s2 += __shfl_down_sync(0xffffffffu, s2, o);
    }
    __shared__ float shs[8], shs2[8];
    int lane = threadIdx.x & 31, w = threadIdx.x >> 5;
    if (lane == 0) { shs[w] = s; shs2[w] = s2; }
    __syncthreads();
    __shared__ float mm, rr;
    if (threadIdx.x == 0) {
        float ts = 0.f, ts2 = 0.f;
        #pragma unroll
        for (int i = 0; i < 8; i++) { ts += shs[i]; ts2 += shs2[i]; }
        float inv_n = 1.f / (float)(NCPG * NHW);
        float mean = ts * inv_n;
        float var  = ts2 * inv_n - mean * mean;
        mm = mean; rr = rsqrtf(var + EPSV);
    }
    __syncthreads();
    if (threadIdx.x < NCPG) {
        int ch = g * NCPG + threadIdx.x;
        float wv = gw[ch], bv = gb[ch];
        g_sc[b * ND + ch] = rr * wv;
        g_sh[b * ND + ch] = bv - mm * rr * wv;
    }
}

// ---------------------------------------------------------------------------
// x [b][c][p] --(GN affine + transpose)--> xn hi/lo [b][p][c]
// block (32,8), grid (HW/32, D/32, B)
// ---------------------------------------------------------------------------
__global__ void xn_conv_k(const float* __restrict__ x)
{
    __shared__ float t[32][33];
    int b = blockIdx.z, p0 = blockIdx.x * 32, c0 = blockIdx.y * 32;
    int tx = threadIdx.x, ty = threadIdx.y;
    const float* xb = x + (size_t)b * ND * NHW;
    #pragma unroll
    for (int r = 0; r < 4; r++) {
        int c = c0 + ty + 8 * r;
        t[ty + 8 * r][tx] = xb[(size_t)c * NHW + p0 + tx] * g_sc[b * ND + c] + g_sh[b * ND + c];
    }
    __syncthreads();
    #pragma unroll
    for (int r = 0; r < 4; r++) {
        int p = p0 + ty + 8 * r;
        int c = c0 + tx;
        float v = t[tx][ty + 8 * r];
        bf16 h, l; split1(v, h, l);
        size_t o = ((size_t)b * NHW + p) * ND + c;
        g_xnh[o] = h; g_xnl[o] = l;
    }
}

// ---------------------------------------------------------------------------
// LayerNorm on context rows -> cn hi/lo
// ---------------------------------------------------------------------------
__global__ void ln_k(const float* __restrict__ ctx,
                     const float* __restrict__ lw,
                     const float* __restrict__ lb)
{
    int row = blockIdx.x;
    const float* p = ctx + (size_t)row * NCTX;
    float v[3];
    float s = 0.f, s2 = 0.f;
    #pragma unroll
    for (int r = 0; r < 3; r++) {
        v[r] = p[threadIdx.x + r * 256];
        s += v[r]; s2 += v[r] * v[r];
    }
    #pragma unroll
    for (int o = 16; o > 0; o >>= 1) {
        s  += __shfl_down_sync(0xffffffffu, s,  o);
        s2 += __shfl_down_sync(0xffffffffu, s2, o);
    }
    __shared__ float shs[8], shs2[8];
    int lane = threadIdx.x & 31, w = threadIdx.x >> 5;
    if (lane == 0) { shs[w] = s; shs2[w] = s2; }
    __syncthreads();
    __shared__ float mm, rr;
    if (threadIdx.x == 0) {
        float ts = 0.f, ts2 = 0.f;
        #pragma unroll
        for (int i = 0; i < 8; i++) { ts += shs[i]; ts2 += shs2[i]; }
        float inv_n = 1.f / (float)NCTX;
        float mean = ts * inv_n;
        float var  = ts2 * inv_n - mean * mean;
        mm = mean; rr = rsqrtf(var + EPSV);
    }
    __syncthreads();
    #pragma unroll
    for (int r = 0; r < 3; r++) {
        int i = threadIdx.x + r * 256;
        float val = (v[r] - mm) * rr * lw[i] + lb[i];
        bf16 h, l; split1(val, h, l);
        size_t o = (size_t)row * NCTX + i;
        g_cnh[o] = h; g_cnl[o] = l;
    }
}

// ---------------------------------------------------------------------------
// weight fp32 -> hi/lo planes (elementwise)
// ---------------------------------------------------------------------------
__global__ void convw_k(const float* __restrict__ w, bf16* __restrict__ hi,
                        bf16* __restrict__ lo, int n)
{
    int i = blockIdx.x * 256 + threadIdx.x;
    if (i < n) {
        bf16 h, l; split1(w[i], h, l);
        hi[i] = h; lo[i] = l;
    }
}

// ---------------------------------------------------------------------------
// Softmax over j (S=256), reads fp32 sim, writes P hi/lo. One warp per row.
// ---------------------------------------------------------------------------
__global__ void softmax_k()
{
    size_t row = (size_t)blockIdx.x * 8 + (threadIdx.x >> 5);
    int lane = threadIdx.x & 31;
    const float* p = g_sim + row * NS;
    float4 v0 = *(const float4*)(p + lane * 4);
    float4 v1 = *(const float4*)(p + 128 + lane * 4);
    float m = fmaxf(fmaxf(fmaxf(v0.x, v0.y), fmaxf(v0.z, v0.w)),
                    fmaxf(fmaxf(v1.x, v1.y), fmaxf(v1.z, v1.w)));
    #pragma unroll
    for (int o = 16; o > 0; o >>= 1) m = fmaxf(m, __shfl_xor_sync(0xffffffffu, m, o));
    v0.x = __expf(v0.x - m); v0.y = __expf(v0.y - m);
    v0.z = __expf(v0.z - m); v0.w = __expf(v0.w - m);
    v1.x = __expf(v1.x - m); v1.y = __expf(v1.y - m);
    v1.z = __expf(v1.z - m); v1.w = __expf(v1.w - m);
    float s = v0.x + v0.y + v0.z + v0.w + v1.x + v1.y + v1.z + v1.w;
    #pragma unroll
    for (int o = 16; o > 0; o >>= 1) s += __shfl_xor_sync(0xffffffffu, s, o);
    float inv = 1.f / s;
    float vv[8] = {v0.x*inv, v0.y*inv, v0.z*inv, v0.w*inv,
                   v1.x*inv, v1.y*inv, v1.z*inv, v1.w*inv};
    bf16* Ph = g_Ph + row * NS;
    bf16* Pl = g_Pl + row * NS;
    #pragma unroll
    for (int half = 0; half < 2; half++) {
        int base = half * 128 + lane * 4;
        #pragma unroll
        for (int e = 0; e < 4; e++) {
            bf16 h, l; split1(vv[half * 4 + e], h, l);
            Ph[base + e] = h; Pl[base + e] = l;
        }
    }
}

// ---------------------------------------------------------------------------
// PTX helpers
// ---------------------------------------------------------------------------
__device__ __forceinline__ void mma16816(float* d, const uint32_t* a, const uint32_t* b)
{
    asm volatile(
        "mma.sync.aligned.m16n8k16.row.col.f32.bf16.bf16.f32 "
        "{%0,%1,%2,%3},{%4,%5,%6,%7},{%8,%9},{%0,%1,%2,%3};"
        : "+f"(d[0]), "+f"(d[1]), "+f"(d[2]), "+f"(d[3])
        : "r"(a[0]), "r"(a[1]), "r"(a[2]), "r"(a[3]), "r"(b[0]), "r"(b[1]));
}
__device__ __forceinline__ void ldsm4(uint32_t& r0, uint32_t& r1, uint32_t& r2,
                                      uint32_t& r3, uint32_t addr)
{
    asm volatile("ldmatrix.sync.aligned.m8n8.x4.shared.b16 {%0,%1,%2,%3},[%4];"
        : "=r"(r0), "=r"(r1), "=r"(r2), "=r"(r3) : "r"(addr));
}
__device__ __forceinline__ void cpa16(uint32_t saddr, const void* gaddr)
{
    asm volatile("cp.async.cg.shared.global [%0],[%1],16;" :: "r"(saddr), "l"(gaddr));
}
__device__ __forceinline__ void cp_commit() { asm volatile("cp.async.commit_group;" ::: "memory"); }

// ---------------------------------------------------------------------------
// bf16 hi/lo GEMM: C[M,N] = alpha * A(MxK) * B(KxN)
// A planes [m][k] (lda, k-contig), B planes [n][k] (ldb, k-contig).
// Block 128x128, BK=16, 256 threads (warp tile 64x32), cp.async 3-stage.
// EPI 0: fp32 C[m*ldc+n] = alpha*acc (+bias[n])
// EPI 1: bf16 hi/lo C[m*ldc+n] = acc (+bias[n])
// EPI 2: bf16 hi/lo C[m*ldc+n] = acc + bias[m]
// EPI 3: fp32 C[m*ldc+n] = acc + bias[m] + resid[m*ldc+n]
// ---------------------------------------------------------------------------
constexpr int PLANE_B = 128 * 12 * 4;     // 6144 bytes per plane
constexpr int STAGE_B = PLANE_B * 4;      // 24576 bytes per stage
constexpr int SMEM_B  = STAGE_B * 3;      // 73728 bytes

template<int EPI>
__global__ __launch_bounds__(256, 2)
void gemm_bf16(const bf16* __restrict__ Ah, const bf16* __restrict__ Al,
               const bf16* __restrict__ Bh, const bf16* __restrict__ Bl,
               void* __restrict__ C0, void* __restrict__ C1,
               const float* __restrict__ bias, const float* __restrict__ resid,
               float alpha, int K, int lda, int ldb, int ldc,
               long sA, long sB, long sC)
{
    extern __shared__ __align__(16) uint32_t dsm[];
    uint32_t smemU;
    asm("{.reg .u64 t; cvta.to.shared.u64 t, %1; cvt.u32.u64 %0, t;}"
        : "=r"(smemU) : "l"(dsm));

    const int tid  = threadIdx.x;
    const int lane = tid & 31, wid = tid >> 5;
    const int bz   = blockIdx.z;
    const int m0 = blockIdx.x * 128;
    const int n0 = blockIdx.y * 128;

    const bf16* ApH = Ah + (size_t)bz * sA;
    const bf16* ApL = Al + (size_t)bz * sA;
    const bf16* BpH = Bh + (size_t)bz * sB;
    const bf16* BpL = Bl + (size_t)bz * sB;

    const int nIter = K >> 4;

    const int lrow = tid >> 1, lch = tid & 1;
    const uint32_t so = (uint32_t)(lrow * 12 + lch * 4) * 4;
    const size_t gA = (size_t)(m0 + lrow) * lda + lch * 8;
    const size_t gB = (size_t)(n0 + lrow) * ldb + lch * 8;

    auto issue = [&](int it, int st) {
        int k0 = it << 4;
        uint32_t sb = smemU + st * STAGE_B;
        cpa16(sb + so,               ApH + gA + k0);
        cpa16(sb + PLANE_B + so,     ApL + gA + k0);
        cpa16(sb + 2 * PLANE_B + so, BpH + gB + k0);
        cpa16(sb + 3 * PLANE_B + so, BpL + gB + k0);
        cp_commit();
    };

    // warp layout
    const int mw = (wid & 1) * 64, nw = (wid >> 1) * 32;
    const int lr = lane & 7;
    const uint32_t aoff = (uint32_t)(((mw + lr + 8 * ((lane >> 3) & 1)) * 12
                                      + (lane >> 4) * 4) * 4);
    const uint32_t boff = (uint32_t)(((nw + 8 * (lane >> 4) + lr) * 12
                                      + ((lane >> 3) & 1) * 4) * 4);
    const int g = lane >> 2, tg = lane & 3;

    float acc[4][4][4];
    #pragma unroll
    for (int i = 0; i < 4; i++)
        #pragma unroll
        for (int j = 0; j < 4; j++)
            #pragma unroll
            for (int q = 0; q < 4; q++) acc[i][j][q] = 0.f;

    issue(0, 0);
    issue(1, 1);

    for (int it = 0; it < nIter; it++) {
        if (it + 1 < nIter) asm volatile("cp.async.wait_group 1;" ::: "memory");
        else                asm volatile("cp.async.wait_group 0;" ::: "memory");
        __syncthreads();
        if (it + 2 < nIter) issue(it + 2, (it + 2) % 3);

        uint32_t sb = smemU + (it % 3) * STAGE_B;
        uint32_t aH = sb, aL = sb + PLANE_B;
        uint32_t bH = sb + 2 * PLANE_B, bL = sb + 3 * PLANE_B;

        uint32_t bh[4][2], bl[4][2], af[4][4];
        ldsm4(bh[0][0], bh[0][1], bh[1][0], bh[1][1], bH + boff);
        ldsm4(bh[2][0], bh[2][1], bh[3][0], bh[3][1], bH + boff + 768);
        ldsm4(bl[0][0], bl[0][1], bl[1][0], bl[1][1], bL + boff);
        ldsm4(bl[2][0], bl[2][1], bl[3][0], bl[3][1], bL + boff + 768);
        #pragma unroll
        for (int i = 0; i < 4; i++)
            ldsm4(af[i][0], af[i][1], af[i][2], af[i][3], aH + aoff + i * 768);
        #pragma unroll
        for (int i = 0; i < 4; i++)
            #pragma unroll
            for (int j = 0; j < 4; j++)
                mma16816(acc[i][j], af[i], bh[j]);
        #pragma unroll
        for (int i = 0; i < 4; i++)
            #pragma unroll
            for (int j = 0; j < 4; j++)
                mma16816(acc[i][j], af[i], bl[j]);
        #pragma unroll
        for (int i = 0; i < 4; i++)
            ldsm4(af[i][0], af[i][1], af[i][2], af[i][3], aL + aoff + i * 768);
        #pragma unroll
        for (int i = 0; i < 4; i++)
            #pragma unroll
            for (int j = 0; j < 4; j++)
                mma16816(acc[i][j], af[i], bh[j]);
    }

    // ------------------- epilogue -------------------
    if constexpr (EPI == 0) {
        float* Co = (float*)C0 + (size_t)bz * sC;
        #pragma unroll
        for (int i = 0; i < 4; i++) {
            int r = m0 + mw + 16 * i + g;
            #pragma unroll
            for (int j = 0; j < 4; j++) {
                int c = n0 + nw + 8 * j + 2 * tg;
                float b0v = bias ? bias[c] : 0.f, b1v = bias ? bias[c + 1] : 0.f;
                float2 v0 = make_float2(alpha * acc[i][j][0] + b0v,
                                        alpha * acc[i][j][1] + b1v);
                float2 v1 = make_float2(alpha * acc[i][j][2] + b0v,
                                        alpha * acc[i][j][3] + b1v);
                *(float2*)(Co + (size_t)r * ldc + c)       = v0;
                *(float2*)(Co + (size_t)(r + 8) * ldc + c) = v1;
            }
        }
    } else if constexpr (EPI == 1 || EPI == 2) {
        bf16* Ch = (bf16*)C0 + (size_t)bz * sC;
        bf16* Cl = (bf16*)C1 + (size_t)bz * sC;
        #pragma unroll
        for (int i = 0; i < 4; i++) {
            int r = m0 + mw + 16 * i + g;
            #pragma unroll
            for (int j = 0; j < 4; j++) {
                int c = n0 + nw + 8 * j + 2 * tg;
                float b0v, b1v, b2v, b3v;
                if constexpr (EPI == 1) {
                    b0v = bias ? bias[c] : 0.f; b1v = bias ? bias[c + 1] : 0.f;
                    b2v = b0v; b3v = b1v;
                } else {
                    b0v = b1v = bias[r]; b2v = b3v = bias[r + 8];
                }
                float v0 = acc[i][j][0] + b0v, v1 = acc[i][j][1] + b1v;
                float v2 = acc[i][j][2] + b2v, v3 = acc[i][j][3] + b3v;
                bf16 h0, l0, h1, l1, h2, l2, h3, l3;
                split1(v0, h0, l0); split1(v1, h1, l1);
                split1(v2, h2, l2); split1(v3, h3, l3);
                *(__nv_bfloat162*)(Ch + (size_t)r * ldc + c)       = __nv_bfloat162(h0, h1);
                *(__nv_bfloat162*)(Cl + (size_t)r * ldc + c)       = __nv_bfloat162(l0, l1);
                *(__nv_bfloat162*)(Ch + (size_t)(r + 8) * ldc + c) = __nv_bfloat162(h2, h3);
                *(__nv_bfloat162*)(Cl + (size_t)(r + 8) * ldc + c) = __nv_bfloat162(l2, l3);
            }
        }
    } else { // EPI == 3
        float* Co = (float*)C0 + (size_t)bz * sC;
        const float* R = resid + (size_t)bz * sC;
        #pragma unroll
        for (int i = 0; i < 4; i++) {
            int r = m0 + mw + 16 * i + g;
            float bv0 = bias[r], bv1 = bias[r + 8];
            #pragma unroll
            for (int j = 0; j < 4; j++) {
                int c = n0 + nw + 8 * j + 2 * tg;
                float2 rv0 = *(const float2*)(R + (size_t)r * ldc + c);
                float2 rv1 = *(const float2*)(R + (size_t)(r + 8) * ldc + c);
                float2 v0 = make_float2(acc[i][j][0] + bv0 + rv0.x,
                                        acc[i][j][1] + bv0 + rv0.y);
                float2 v1 = make_float2(acc[i][j][2] + bv1 + rv1.x,
                                        acc[i][j][3] + bv1 + rv1.y);
                *(float2*)(Co + (size_t)r * ldc + c)       = v0;
                *(float2*)(Co + (size_t)(r + 8) * ldc + c) = v1;
            }
        }
    }
}

// ---------------------------------------------------------------------------
extern "C" void kernel_launch(void* const* d_in, const int* in_sizes, int n_in,
                              void* d_out, int out_size)
{
    const float* x    = (const float*)d_in[0];
    const float* ctx  = (const float*)d_in[1];
    const float* gn_w = (const float*)d_in[2];
    const float* gn_b = (const float*)d_in[3];
    const float* ln_w = (const float*)d_in[4];
    const float* ln_b = (const float*)d_in[5];
    const float* wq   = (const float*)d_in[6];
    const float* bq   = (const float*)d_in[7];
    const float* wkv  = (const float*)d_in[8];
    const float* bkv  = (const float*)d_in[9];
    const float* wo   = (const float*)d_in[10];
    const float* bo   = (const float*)d_in[11];
    float* out = (float*)d_out;

    static bool attr_done = false;
    if (!attr_done) {
        cudaFuncSetAttribute(gemm_bf16<0>, cudaFuncAttributeMaxDynamicSharedMemorySize, SMEM_B);
        cudaFuncSetAttribute(gemm_bf16<1>, cudaFuncAttributeMaxDynamicSharedMemorySize, SMEM_B);
        cudaFuncSetAttribute(gemm_bf16<2>, cudaFuncAttributeMaxDynamicSharedMemorySize, SMEM_B);
        cudaFuncSetAttribute(gemm_bf16<3>, cudaFuncAttributeMaxDynamicSharedMemorySize, SMEM_B);
        attr_done = true;
    }

    bf16 *xnh, *xnl, *qh, *ql, *aoh, *aol, *Ph, *Pl;
    bf16 *cnh, *cnl, *kh, *kl, *vh, *vl;
    bf16 *wqh, *wql, *wkvh, *wkvl, *woh, *wol;
    float* sim;
    cudaGetSymbolAddress((void**)&xnh, g_xnh);  cudaGetSymbolAddress((void**)&xnl, g_xnl);
    cudaGetSymbolAddress((void**)&qh,  g_qh);   cudaGetSymbolAddress((void**)&ql,  g_ql);
    cudaGetSymbolAddress((void**)&aoh, g_aoh);  cudaGetSymbolAddress((void**)&aol, g_aol);
    cudaGetSymbolAddress((void**)&Ph,  g_Ph);   cudaGetSymbolAddress((void**)&Pl,  g_Pl);
    cudaGetSymbolAddress((void**)&cnh, g_cnh);  cudaGetSymbolAddress((void**)&cnl, g_cnl);
    cudaGetSymbolAddress((void**)&kh,  g_kh);   cudaGetSymbolAddress((void**)&kl,  g_kl);
    cudaGetSymbolAddress((void**)&vh,  g_vh);   cudaGetSymbolAddress((void**)&vl,  g_vl);
    cudaGetSymbolAddress((void**)&wqh, g_wqh);  cudaGetSymbolAddress((void**)&wql, g_wql);
    cudaGetSymbolAddress((void**)&wkvh, g_wkvh); cudaGetSymbolAddress((void**)&wkvl, g_wkvl);
    cudaGetSymbolAddress((void**)&woh, g_woh);  cudaGetSymbolAddress((void**)&wol, g_wol);
    cudaGetSymbolAddress((void**)&sim, g_sim);

    const float qscale = 0.044194173824159216f; // 512^-0.5

    // --- prep kernels ---
    gn_stats_k<<<NB * 32, 256>>>(x, gn_w, gn_b);
    ln_k<<<NB * NS, 256>>>(ctx, ln_w, ln_b);
    convw_k<<<(ND * ND + 255) / 256, 256>>>(wq, wqh, wql, ND * ND);
    convw_k<<<(1024 * NCTX + 255) / 256, 256>>>(wkv, wkvh, wkvl, 1024 * NCTX);
    convw_k<<<(ND * ND + 255) / 256, 256>>>(wo, woh, wol, ND * ND);
    xn_conv_k<<<dim3(NHW / 32, ND / 32, NB), dim3(32, 8)>>>(x);

    // --- K proj: k[s][c] = cn @ wkv[0:512]^T + bkv[0:512] ---
    gemm_bf16<1><<<dim3(NS / 128, ND / 128, NB), 256, SMEM_B>>>(
        cnh, cnl, wkvh, wkvl, kh, kl, bkv, nullptr,
        1.f, NCTX, NCTX, NCTX, ND,
        (long)NS * NCTX, 0L, (long)NS * ND);

    // --- V proj (transposed): v[c][s] = wkv[512:1024] @ cn^T + bkv[512+c] ---
    gemm_bf16<2><<<dim3(ND / 128, NS / 128, NB), 256, SMEM_B>>>(
        wkvh + (size_t)512 * NCTX, wkvl + (size_t)512 * NCTX, cnh, cnl, vh, vl,
        bkv + 512, nullptr,
        1.f, NCTX, NCTX, NCTX, NS,
        0L, (long)NS * NCTX, (long)ND * NS);

    // --- Q proj: q[p][c] = xn @ wq^T + bq ---
    gemm_bf16<1><<<dim3(NHW / 128, ND / 128, NB), 256, SMEM_B>>>(
        xnh, xnl, wqh, wql, qh, ql, bq, nullptr,
        1.f, ND, ND, ND, ND,
        (long)NHW * ND, 0L, (long)NHW * ND);

    // --- sim[p][j] = qscale * q @ k^T ---
    gemm_bf16<0><<<dim3(NHW / 128, NS / 128, NB), 256, SMEM_B>>>(
        qh, ql, kh, kl, sim, nullptr, nullptr, nullptr,
        qscale, ND, ND, ND, NS,
        (long)NHW * ND, (long)NS * ND, (long)NHW * NS);

    // --- softmax -> P hi/lo ---
    softmax_k<<<NB * NHW / 8, 256>>>();

    // --- PV: ao[p][c] = P @ v^T  (v stored [c][s]) ---
    gemm_bf16<1><<<dim3(NHW / 128, ND / 128, NB), 256, SMEM_B>>>(
        Ph, Pl, vh, vl, aoh, aol, nullptr, nullptr,
        1.f, NS, NS, NS, ND,
        (long)NHW * NS, (long)ND * NS, (long)NHW * ND);

    // --- O proj (transposed): out[c][p] = wo @ ao^T + bo[c] + x[c][p] ---
    gemm_bf16<3><<<dim3(ND / 128, NHW / 128, NB), 256, SMEM_B>>>(
        woh, wol, aoh, aol, out, nullptr, bo, x,
        1.f, ND, ND, ND, NHW,
        0L, (long)NHW * ND, (long)ND * NHW);
}

// round 12
// speedup vs baseline: 2.8621x; 1.4516x over previous
#include <cuda_runtime.h>
#include <cuda_fp16.h>
#include <cstdint>

// ---------------------------------------------------------------------------
// CrossAttention, fp16 2-product split GEMMs (legacy mma.sync path, sm_103).
// D = Ah*Bh + Ah*Bl  (A single fp16 plane, B hi/lo fp16 planes), err ~2^-11.
// sim -> softmax -> P fused into one kernel (no fp32 sim round-trip).
// ---------------------------------------------------------------------------

constexpr int NB   = 16;
constexpr int ND   = 512;
constexpr int NHW  = 4096;
constexpr int NS   = 256;
constexpr int NCTX = 768;
constexpr int NCPG = 16;
#define EPSV 1e-5f

typedef __half h16;

// ---- scratch (device globals; allocation-free) ----
__device__ float g_sc[NB * ND];
__device__ float g_sh[NB * ND];
__device__ __align__(256) h16 g_xnh[(size_t)NB * NHW * ND];   // A of Qproj (hi only)
__device__ __align__(256) h16 g_qh [(size_t)NB * NHW * ND];   // A of sim   (hi only)
__device__ __align__(256) h16 g_Ph [(size_t)NB * NHW * NS];   // A of PV    (hi only)
__device__ __align__(256) h16 g_aoh[(size_t)NB * NHW * ND];   // B of Oproj hi
__device__ __align__(256) h16 g_aol[(size_t)NB * NHW * ND];   //            lo
__device__ __align__(256) h16 g_cnh[NB * NS * NCTX];          // A of Kproj / B of Vproj
__device__ __align__(256) h16 g_cnl[NB * NS * NCTX];
__device__ __align__(256) h16 g_kh [NB * NS * ND];            // B of sim
__device__ __align__(256) h16 g_kl [NB * NS * ND];
__device__ __align__(256) h16 g_vh [NB * ND * NS];            // B of PV  ([c][s])
__device__ __align__(256) h16 g_vl [NB * ND * NS];
__device__ __align__(256) h16 g_wqh [ND * ND];                // B of Qproj
__device__ __align__(256) h16 g_wql [ND * ND];
__device__ __align__(256) h16 g_wkvh[1024 * NCTX];            // rows<512: B of Kproj; rows>=512: A of Vproj
__device__ __align__(256) h16 g_wkvl[1024 * NCTX];
__device__ __align__(256) h16 g_woh [ND * ND];                // A of Oproj (hi only)

__device__ __forceinline__ void split1(float v, h16& h, h16& l)
{
    h = __float2half_rn(v);
    l = __float2half_rn(v - __half2float(h));
}

// ---------------------------------------------------------------------------
// GroupNorm stats -> per-(b,c) scale/shift
// ---------------------------------------------------------------------------
__global__ void gn_stats_k(const float* __restrict__ x,
                           const float* __restrict__ gw,
                           const float* __restrict__ gb)
{
    int bg = blockIdx.x;
    int b = bg >> 5, g = bg & 31;
    const float4* p4 = (const float4*)(x + (size_t)bg * (NCPG * NHW));
    float s = 0.f, s2 = 0.f;
    const int n4 = NCPG * NHW / 4;
    for (int i = threadIdx.x; i < n4; i += 256) {
        float4 v = p4[i];
        s  += v.x + v.y + v.z + v.w;
        s2 += v.x*v.x + v.y*v.y + v.z*v.z + v.w*v.w;
    }
    #pragma unroll
    for (int o = 16; o > 0; o >>= 1) {
        s  += __shfl_down_sync(0xffffffffu, s,  o);
        s2 += __shfl_down_sync(0xffffffffu, s2, o);
    }
    __shared__ float shs[8], shs2[8];
    int lane = threadIdx.x & 31, w = threadIdx.x >> 5;
    if (lane == 0) { shs[w] = s; shs2[w] = s2; }
    __syncthreads();
    __shared__ float mm, rr;
    if (threadIdx.x == 0) {
        float ts = 0.f, ts2 = 0.f;
        #pragma unroll
        for (int i = 0; i < 8; i++) { ts += shs[i]; ts2 += shs2[i]; }
        float inv_n = 1.f / (float)(NCPG * NHW);
        float mean = ts * inv_n;
        float var  = ts2 * inv_n - mean * mean;
        mm = mean; rr = rsqrtf(var + EPSV);
    }
    __syncthreads();
    if (threadIdx.x < NCPG) {
        int ch = g * NCPG + threadIdx.x;
        float wv = gw[ch], bv = gb[ch];
        g_sc[b * ND + ch] = rr * wv;
        g_sh[b * ND + ch] = bv - mm * rr * wv;
    }
}

// ---------------------------------------------------------------------------
// x [b][c][p] --(GN affine + transpose)--> xn fp16 [b][p][c]
// ---------------------------------------------------------------------------
__global__ void xn_conv_k(const float* __restrict__ x)
{
    __shared__ float t[32][33];
    int b = blockIdx.z, p0 = blockIdx.x * 32, c0 = blockIdx.y * 32;
    int tx = threadIdx.x, ty = threadIdx.y;
    const float* xb = x + (size_t)b * ND * NHW;
    #pragma unroll
    for (int r = 0; r < 4; r++) {
        int c = c0 + ty + 8 * r;
        t[ty + 8 * r][tx] = xb[(size_t)c * NHW + p0 + tx] * g_sc[b * ND + c] + g_sh[b * ND + c];
    }
    __syncthreads();
    #pragma unroll
    for (int r = 0; r < 4; r++) {
        int p = p0 + ty + 8 * r;
        int c = c0 + tx;
        size_t o = ((size_t)b * NHW + p) * ND + c;
        g_xnh[o] = __float2half_rn(t[tx][ty + 8 * r]);
    }
}

// ---------------------------------------------------------------------------
// LayerNorm on context rows -> cn hi/lo
// ---------------------------------------------------------------------------
__global__ void ln_k(const float* __restrict__ ctx,
                     const float* __restrict__ lw,
                     const float* __restrict__ lb)
{
    int row = blockIdx.x;
    const float* p = ctx + (size_t)row * NCTX;
    float v[3];
    float s = 0.f, s2 = 0.f;
    #pragma unroll
    for (int r = 0; r < 3; r++) {
        v[r] = p[threadIdx.x + r * 256];
        s += v[r]; s2 += v[r] * v[r];
    }
    #pragma unroll
    for (int o = 16; o > 0; o >>= 1) {
        s  += __shfl_down_sync(0xffffffffu, s,  o);
        s2 += __shfl_down_sync(0xffffffffu, s2, o);
    }
    __shared__ float shs[8], shs2[8];
    int lane = threadIdx.x & 31, w = threadIdx.x >> 5;
    if (lane == 0) { shs[w] = s; shs2[w] = s2; }
    __syncthreads();
    __shared__ float mm, rr;
    if (threadIdx.x == 0) {
        float ts = 0.f, ts2 = 0.f;
        #pragma unroll
        for (int i = 0; i < 8; i++) { ts += shs[i]; ts2 += shs2[i]; }
        float inv_n = 1.f / (float)NCTX;
        float mean = ts * inv_n;
        float var  = ts2 * inv_n - mean * mean;
        mm = mean; rr = rsqrtf(var + EPSV);
    }
    __syncthreads();
    #pragma unroll
    for (int r = 0; r < 3; r++) {
        int i = threadIdx.x + r * 256;
        float val = (v[r] - mm) * rr * lw[i] + lb[i];
        h16 h, l; split1(val, h, l);
        size_t o = (size_t)row * NCTX + i;
        g_cnh[o] = h; g_cnl[o] = l;
    }
}

// ---------------------------------------------------------------------------
// weights fp32 -> hi/lo fp16 planes (and hi-only variant)
// ---------------------------------------------------------------------------
__global__ void convw_k(const float* __restrict__ w, h16* __restrict__ hi,
                        h16* __restrict__ lo, int n)
{
    int i = blockIdx.x * 256 + threadIdx.x;
    if (i < n) {
        h16 h, l; split1(w[i], h, l);
        hi[i] = h; lo[i] = l;
    }
}
__global__ void convw1_k(const float* __restrict__ w, h16* __restrict__ hi, int n)
{
    int i = blockIdx.x * 256 + threadIdx.x;
    if (i < n) hi[i] = __float2half_rn(w[i]);
}

// ---------------------------------------------------------------------------
// PTX helpers
// ---------------------------------------------------------------------------
__device__ __forceinline__ uint32_t smem_u32(const void* p) {
    uint32_t a;
    asm("{.reg .u64 t; cvta.to.shared.u64 t, %1; cvt.u32.u64 %0, t;}" : "=r"(a) : "l"(p));
    return a;
}
__device__ __forceinline__ void mma16816(float* d, const uint32_t* a, const uint32_t* b)
{
    asm volatile(
        "mma.sync.aligned.m16n8k16.row.col.f32.f16.f16.f32 "
        "{%0,%1,%2,%3},{%4,%5,%6,%7},{%8,%9},{%0,%1,%2,%3};"
        : "+f"(d[0]), "+f"(d[1]), "+f"(d[2]), "+f"(d[3])
        : "r"(a[0]), "r"(a[1]), "r"(a[2]), "r"(a[3]), "r"(b[0]), "r"(b[1]));
}
__device__ __forceinline__ void ldsm4(uint32_t& r0, uint32_t& r1, uint32_t& r2,
                                      uint32_t& r3, uint32_t addr)
{
    asm volatile("ldmatrix.sync.aligned.m8n8.x4.shared.b16 {%0,%1,%2,%3},[%4];"
        : "=r"(r0), "=r"(r1), "=r"(r2), "=r"(r3) : "r"(addr));
}
__device__ __forceinline__ void cpa16(uint32_t saddr, const void* gaddr)
{
    asm volatile("cp.async.cg.shared.global [%0],[%1],16;" :: "r"(saddr), "l"(gaddr));
}
#define CP_COMMIT() asm volatile("cp.async.commit_group;" ::: "memory")

// ---------------------------------------------------------------------------
// Generic fp16 2-product GEMM: C[M,N] = A(MxK)*B(KxN)
// A plane [m][k] fp16 (hi); B planes [n][k] fp16 hi/lo (k contiguous).
// Block 128x128, BK=16, 256 threads (8 warps, warp tile 64x32), 3-stage cp.async.
// EPI 1: fp16 C[m*ldc+n] = acc (+bias[n]); lo plane too if WLO.
// EPI 2: fp16 C = acc + bias[m]; (+lo if WLO)
// EPI 3: fp32 C = acc + bias[m] + resid[m*ldc+n]
// ---------------------------------------------------------------------------
constexpr int PLA  = 128 * 12 * 4;   // 6144 B per plane (128 rows x 12 words)
constexpr int GST  = 3 * PLA;        // 18432 per stage (A, Bh, Bl)
constexpr int GSM  = 3 * GST;        // 55296 total

template<int EPI, int WLO>
__global__ __launch_bounds__(256, 2)
void gemm_fp16(const h16* __restrict__ Ah, const h16* __restrict__ Bh,
               const h16* __restrict__ Bl,
               void* __restrict__ C0, void* __restrict__ C1,
               const float* __restrict__ bias, const float* __restrict__ resid,
               int K, int lda, int ldb, int ldc,
               long sA, long sB, long sC)
{
    extern __shared__ __align__(16) char dsm[];
    const uint32_t sbase = smem_u32(dsm);
    const int tid = threadIdx.x, lane = tid & 31, wid = tid >> 5;
    const int bz = blockIdx.z;
    const int m0 = blockIdx.x * 128;
    const int n0 = blockIdx.y * 128;

    const h16* Ap  = Ah + (size_t)bz * sA;
    const h16* BpH = Bh + (size_t)bz * sB;
    const h16* BpL = Bl + (size_t)bz * sB;
    const int nIter = K >> 4;

    const int lrow = tid >> 1, lch = tid & 1;
    const uint32_t so = (uint32_t)((lrow * 12 + lch * 4) * 4);
    const size_t gAo = (size_t)(m0 + lrow) * lda + lch * 8;
    const size_t gBo = (size_t)(n0 + lrow) * ldb + lch * 8;

    auto issue = [&](int s) {
        int k0 = s << 4;
        uint32_t st = sbase + (s % 3) * GST;
        cpa16(st + so,           Ap  + gAo + k0);
        cpa16(st + PLA + so,     BpH + gBo + k0);
        cpa16(st + 2 * PLA + so, BpL + gBo + k0);
        CP_COMMIT();
    };

    const int mw = (wid & 1) * 64, nw = (wid >> 1) * 32;
    const int lr = lane & 7;
    const uint32_t aoff = (uint32_t)(((mw + lr + 8 * ((lane >> 3) & 1)) * 12
                                      + (lane >> 4) * 4) * 4);
    const uint32_t boff = (uint32_t)(((nw + 8 * (lane >> 4) + lr) * 12
                                      + ((lane >> 3) & 1) * 4) * 4);
    const int g = lane >> 2, tg = lane & 3;

    float acc[4][4][4];
    #pragma unroll
    for (int i = 0; i < 4; i++)
        #pragma unroll
        for (int j = 0; j < 4; j++)
            #pragma unroll
            for (int q = 0; q < 4; q++) acc[i][j][q] = 0.f;

    issue(0); issue(1);

    for (int it = 0; it < nIter; it++) {
        if (it + 1 < nIter) asm volatile("cp.async.wait_group 1;" ::: "memory");
        else                asm volatile("cp.async.wait_group 0;" ::: "memory");
        __syncthreads();
        if (it + 2 < nIter) issue(it + 2);

        uint32_t st = sbase + (it % 3) * GST;
        uint32_t aP = st, bHp = st + PLA, bLp = st + 2 * PLA;

        uint32_t af[4][4], bh[4][2], bl[4][2];
        ldsm4(bh[0][0], bh[0][1], bh[1][0], bh[1][1], bHp + boff);
        ldsm4(bh[2][0], bh[2][1], bh[3][0], bh[3][1], bHp + boff + 768);
        ldsm4(bl[0][0], bl[0][1], bl[1][0], bl[1][1], bLp + boff);
        ldsm4(bl[2][0], bl[2][1], bl[3][0], bl[3][1], bLp + boff + 768);
        #pragma unroll
        for (int i = 0; i < 4; i++)
            ldsm4(af[i][0], af[i][1], af[i][2], af[i][3], aP + aoff + i * 768);
        #pragma unroll
        for (int i = 0; i < 4; i++)
            #pragma unroll
            for (int j = 0; j < 4; j++)
                mma16816(acc[i][j], af[i], bh[j]);
        #pragma unroll
        for (int i = 0; i < 4; i++)
            #pragma unroll
            for (int j = 0; j < 4; j++)
                mma16816(acc[i][j], af[i], bl[j]);
    }

    // ------------- epilogue -------------
    if constexpr (EPI == 1 || EPI == 2) {
        h16* Ch = (h16*)C0 + (size_t)bz * sC;
        h16* Cl = WLO ? ((h16*)C1 + (size_t)bz * sC) : nullptr;
        #pragma unroll
        for (int i = 0; i < 4; i++) {
            int r = m0 + mw + 16 * i + g;
            #pragma unroll
            for (int j = 0; j < 4; j++) {
                int c = n0 + nw + 8 * j + 2 * tg;
                float b0, b1, b2, b3;
                if constexpr (EPI == 1) {
                    b0 = bias ? bias[c] : 0.f; b1 = bias ? bias[c + 1] : 0.f;
                    b2 = b0; b3 = b1;
                } else {
                    b0 = b1 = bias[r]; b2 = b3 = bias[r + 8];
                }
                float v0 = acc[i][j][0] + b0, v1 = acc[i][j][1] + b1;
                float v2 = acc[i][j][2] + b2, v3 = acc[i][j][3] + b3;
                if constexpr (WLO) {
                    h16 h0,l0,h1,l1,h2,l2,h3,l3;
                    split1(v0,h0,l0); split1(v1,h1,l1);
                    split1(v2,h2,l2); split1(v3,h3,l3);
                    *(__half2*)(Ch + (size_t)r * ldc + c)       = __halves2half2(h0, h1);
                    *(__half2*)(Cl + (size_t)r * ldc + c)       = __halves2half2(l0, l1);
                    *(__half2*)(Ch + (size_t)(r + 8) * ldc + c) = __halves2half2(h2, h3);
                    *(__half2*)(Cl + (size_t)(r + 8) * ldc + c) = __halves2half2(l2, l3);
                } else {
                    *(__half2*)(Ch + (size_t)r * ldc + c)       = __floats2half2_rn(v0, v1);
                    *(__half2*)(Ch + (size_t)(r + 8) * ldc + c) = __floats2half2_rn(v2, v3);
                }
            }
        }
    } else { // EPI == 3 : fp32 out + bias[m] + residual
        float* Co = (float*)C0 + (size_t)bz * sC;
        const float* R = resid + (size_t)bz * sC;
        #pragma unroll
        for (int i = 0; i < 4; i++) {
            int r = m0 + mw + 16 * i + g;
            float bv0 = bias[r], bv1 = bias[r + 8];
            #pragma unroll
            for (int j = 0; j < 4; j++) {
                int c = n0 + nw + 8 * j + 2 * tg;
                float2 rv0 = *(const float2*)(R + (size_t)r * ldc + c);
                float2 rv1 = *(const float2*)(R + (size_t)(r + 8) * ldc + c);
                float2 v0 = make_float2(acc[i][j][0] + bv0 + rv0.x,
                                        acc[i][j][1] + bv0 + rv0.y);
                float2 v1 = make_float2(acc[i][j][2] + bv1 + rv1.x,
                                        acc[i][j][3] + bv1 + rv1.y);
                *(float2*)(Co + (size_t)r * ldc + c)       = v0;
                *(float2*)(Co + (size_t)(r + 8) * ldc + c) = v1;
            }
        }
    }
}

// ---------------------------------------------------------------------------
// Fused sim -> softmax -> P (fp16).  Tile: 128 queries x full S=256 keys.
// 512 threads (16 warps: 2 m-warps x 8 n-warps, warp tile 64x32), K=512.
// ---------------------------------------------------------------------------
constexpr int SPA  = 128 * 12 * 4;     // 6144 (q plane)
constexpr int SPB  = 256 * 12 * 4;     // 12288 (k planes)
constexpr int SST  = SPA + 2 * SPB;    // 30720 per stage
constexpr int SRED = 3 * SST;          // 92160
constexpr int SSM  = SRED + 2 * 4608;  // + redM/redS (128x9 fp32 each) = 101376

__global__ __launch_bounds__(512, 1)
void sim_softmax_k(const h16* __restrict__ qh, const h16* __restrict__ kh,
                   const h16* __restrict__ kl, float qscale)
{
    extern __shared__ __align__(16) char dsm[];
    const uint32_t sbase = smem_u32(dsm);
    float* redM = (float*)(dsm + SRED);
    float* redS = (float*)(dsm + SRED + 4608);
    const int tid = threadIdx.x, lane = tid & 31, wid = tid >> 5;
    const int b = blockIdx.y, p0 = blockIdx.x * 128;

    const h16* Qp  = qh + (size_t)b * NHW * ND;
    const h16* KpH = kh + (size_t)b * NS * ND;
    const h16* KpL = kl + (size_t)b * NS * ND;

    const int lrow = tid >> 1, lch = tid & 1;
    const uint32_t so = (uint32_t)((lrow * 12 + lch * 4) * 4);

    auto issue = [&](int s) {
        int k0 = s << 4;
        uint32_t st = sbase + (s % 3) * SST;
        if (tid < 256)
            cpa16(st + so, Qp + (size_t)(p0 + lrow) * ND + k0 + lch * 8);
        cpa16(st + SPA + so,       KpH + (size_t)lrow * ND + k0 + lch * 8);
        cpa16(st + SPA + SPB + so, KpL + (size_t)lrow * ND + k0 + lch * 8);
        CP_COMMIT();
    };

    const int mwp = wid & 1, nwp = wid >> 1;
    const int mw = mwp * 64, nw = nwp * 32;
    const int lr = lane & 7;
    const uint32_t aoff = (uint32_t)(((mw + lr + 8 * ((lane >> 3) & 1)) * 12
                                      + (lane >> 4) * 4) * 4);
    const uint32_t boff = (uint32_t)(((nw + 8 * (lane >> 4) + lr) * 12
                                      + ((lane >> 3) & 1) * 4) * 4);
    const int g = lane >> 2, tg = lane & 3;

    float acc[4][4][4];
    #pragma unroll
    for (int i = 0; i < 4; i++)
        #pragma unroll
        for (int j = 0; j < 4; j++)
            #pragma unroll
            for (int q = 0; q < 4; q++) acc[i][j][q] = 0.f;

    const int nIter = ND >> 4;   // 32
    issue(0); issue(1);

    for (int it = 0; it < nIter; it++) {
        if (it + 1 < nIter) asm volatile("cp.async.wait_group 1;" ::: "memory");
        else                asm volatile("cp.async.wait_group 0;" ::: "memory");
        __syncthreads();
        if (it + 2 < nIter) issue(it + 2);

        uint32_t st = sbase + (it % 3) * SST;
        uint32_t aP = st, bHp = st + SPA, bLp = st + SPA + SPB;

        uint32_t af[4][4], bh[4][2], bl[4][2];
        ldsm4(bh[0][0], bh[0][1], bh[1][0], bh[1][1], bHp + boff);
        ldsm4(bh[2][0], bh[2][1], bh[3][0], bh[3][1], bHp + boff + 768);
        ldsm4(bl[0][0], bl[0][1], bl[1][0], bl[1][1], bLp + boff);
        ldsm4(bl[2][0], bl[2][1], bl[3][0], bl[3][1], bLp + boff + 768);
        #pragma unroll
        for (int i = 0; i < 4; i++)
            ldsm4(af[i][0], af[i][1], af[i][2], af[i][3], aP + aoff + i * 768);
        #pragma unroll
        for (int i = 0; i < 4; i++)
            #pragma unroll
            for (int j = 0; j < 4; j++)
                mma16816(acc[i][j], af[i], bh[j]);
        #pragma unroll
        for (int i = 0; i < 4; i++)
            #pragma unroll
            for (int j = 0; j < 4; j++)
                mma16816(acc[i][j], af[i], bl[j]);
    }

    // ---- scale ----
    #pragma unroll
    for (int i = 0; i < 4; i++)
        #pragma unroll
        for (int j = 0; j < 4; j++)
            #pragma unroll
            for (int q = 0; q < 4; q++) acc[i][j][q] *= qscale;

    // ---- row max: per-thread over its cols, shfl over tg, smem over n-warps ----
    float rmx[4][2];
    #pragma unroll
    for (int i = 0; i < 4; i++)
        #pragma unroll
        for (int h = 0; h < 2; h++) {
            float m = -1e30f;
            #pragma unroll
            for (int j = 0; j < 4; j++)
                m = fmaxf(m, fmaxf(acc[i][j][2 * h], acc[i][j][2 * h + 1]));
            rmx[i][h] = m;
        }
    #pragma unroll
    for (int o = 1; o <= 2; o <<= 1)
        #pragma unroll
        for (int i = 0; i < 4; i++)
            #pragma unroll
            for (int h = 0; h < 2; h++)
                rmx[i][h] = fmaxf(rmx[i][h], __shfl_xor_sync(0xffffffffu, rmx[i][h], o));
    if (tg == 0) {
        #pragma unroll
        for (int i = 0; i < 4; i++)
            #pragma unroll
            for (int h = 0; h < 2; h++)
                redM[(mw + 16 * i + 8 * h + g) * 9 + nwp] = rmx[i][h];
    }
    __syncthreads();
    float rM[4][2];
    #pragma unroll
    for (int i = 0; i < 4; i++)
        #pragma unroll
        for (int h = 0; h < 2; h++) {
            int R = mw + 16 * i + 8 * h + g;
            float m = -1e30f;
            #pragma unroll
            for (int w = 0; w < 8; w++) m = fmaxf(m, redM[R * 9 + w]);
            rM[i][h] = m;
        }

    // ---- exp + row sum ----
    float rsm[4][2] = {{0.f,0.f},{0.f,0.f},{0.f,0.f},{0.f,0.f}};
    #pragma unroll
    for (int i = 0; i < 4; i++)
        #pragma unroll
        for (int j = 0; j < 4; j++)
            #pragma unroll
            for (int h = 0; h < 2; h++) {
                float e0 = __expf(acc[i][j][2*h]     - rM[i][h]);
                float e1 = __expf(acc[i][j][2*h + 1] - rM[i][h]);
                acc[i][j][2*h]     = e0;
                acc[i][j][2*h + 1] = e1;
                rsm[i][h] += e0 + e1;
            }
    #pragma unroll
    for (int o = 1; o <= 2; o <<= 1)
        #pragma unroll
        for (int i = 0; i < 4; i++)
            #pragma unroll
            for (int h = 0; h < 2; h++)
                rsm[i][h] += __shfl_xor_sync(0xffffffffu, rsm[i][h], o);
    if (tg == 0) {
        #pragma unroll
        for (int i = 0; i < 4; i++)
            #pragma unroll
            for (int h = 0; h < 2; h++)
                redS[(mw + 16 * i + 8 * h + g) * 9 + nwp] = rsm[i][h];
    }
    __syncthreads();

    h16* Pp = g_Ph + ((size_t)b * NHW + p0) * NS;
    #pragma unroll
    for (int i = 0; i < 4; i++)
        #pragma unroll
        for (int h = 0; h < 2; h++) {
            int R = mw + 16 * i + 8 * h + g;
            float sum = 0.f;
            #pragma unroll
            for (int w = 0; w < 8; w++) sum += redS[R * 9 + w];
            float inv = 1.f / sum;
            #pragma unroll
            for (int j = 0; j < 4; j++) {
                int c = nw + 8 * j + 2 * tg;
                *(__half2*)(Pp + (size_t)R * NS + c) =
                    __floats2half2_rn(acc[i][j][2*h] * inv, acc[i][j][2*h + 1] * inv);
            }
        }
}

// ---------------------------------------------------------------------------
extern "C" void kernel_launch(void* const* d_in, const int* in_sizes, int n_in,
                              void* d_out, int out_size)
{
    const float* x    = (const float*)d_in[0];
    const float* ctx  = (const float*)d_in[1];
    const float* gn_w = (const float*)d_in[2];
    const float* gn_b = (const float*)d_in[3];
    const float* ln_w = (const float*)d_in[4];
    const float* ln_b = (const float*)d_in[5];
    const float* wq   = (const float*)d_in[6];
    const float* bq   = (const float*)d_in[7];
    const float* wkv  = (const float*)d_in[8];
    const float* bkv  = (const float*)d_in[9];
    const float* wo   = (const float*)d_in[10];
    const float* bo   = (const float*)d_in[11];
    float* out = (float*)d_out;

    cudaFuncSetAttribute(gemm_fp16<1,0>, cudaFuncAttributeMaxDynamicSharedMemorySize, GSM);
    cudaFuncSetAttribute(gemm_fp16<1,1>, cudaFuncAttributeMaxDynamicSharedMemorySize, GSM);
    cudaFuncSetAttribute(gemm_fp16<2,1>, cudaFuncAttributeMaxDynamicSharedMemorySize, GSM);
    cudaFuncSetAttribute(gemm_fp16<3,0>, cudaFuncAttributeMaxDynamicSharedMemorySize, GSM);
    cudaFuncSetAttribute(sim_softmax_k,  cudaFuncAttributeMaxDynamicSharedMemorySize, SSM);

    h16 *xnh, *qh, *Ph, *aoh, *aol, *cnh, *cnl, *kh, *kl, *vh, *vl;
    h16 *wqh, *wql, *wkvh, *wkvl, *woh;
    cudaGetSymbolAddress((void**)&xnh, g_xnh);
    cudaGetSymbolAddress((void**)&qh,  g_qh);
    cudaGetSymbolAddress((void**)&Ph,  g_Ph);
    cudaGetSymbolAddress((void**)&aoh, g_aoh);  cudaGetSymbolAddress((void**)&aol, g_aol);
    cudaGetSymbolAddress((void**)&cnh, g_cnh);  cudaGetSymbolAddress((void**)&cnl, g_cnl);
    cudaGetSymbolAddress((void**)&kh,  g_kh);   cudaGetSymbolAddress((void**)&kl,  g_kl);
    cudaGetSymbolAddress((void**)&vh,  g_vh);   cudaGetSymbolAddress((void**)&vl,  g_vl);
    cudaGetSymbolAddress((void**)&wqh, g_wqh);  cudaGetSymbolAddress((void**)&wql, g_wql);
    cudaGetSymbolAddress((void**)&wkvh, g_wkvh); cudaGetSymbolAddress((void**)&wkvl, g_wkvl);
    cudaGetSymbolAddress((void**)&woh, g_woh);

    const float qscale = 0.044194173824159216f; // 512^-0.5

    // --- prep ---
    gn_stats_k<<<NB * 32, 256>>>(x, gn_w, gn_b);
    ln_k<<<NB * NS, 256>>>(ctx, ln_w, ln_b);
    convw_k<<<(ND * ND + 255) / 256, 256>>>(wq, wqh, wql, ND * ND);
    convw_k<<<(1024 * NCTX + 255) / 256, 256>>>(wkv, wkvh, wkvl, 1024 * NCTX);
    convw1_k<<<(ND * ND + 255) / 256, 256>>>(wo, woh, ND * ND);
    xn_conv_k<<<dim3(NHW / 32, ND / 32, NB), dim3(32, 8)>>>(x);

    // --- K proj: k[s][c] = cn @ wkv[0:512]^T + bkv[0:512]  (hi/lo out) ---
    gemm_fp16<1,1><<<dim3(NS / 128, ND / 128, NB), 256, GSM>>>(
        cnh, wkvh, wkvl, kh, kl, bkv, nullptr,
        NCTX, NCTX, NCTX, ND,
        (long)NS * NCTX, 0L, (long)NS * ND);

    // --- V proj (transposed): v[c][s] = wkv[512:] @ cn^T + bkv[512+c] (hi/lo) ---
    gemm_fp16<2,1><<<dim3(ND / 128, NS / 128, NB), 256, GSM>>>(
        wkvh + (size_t)512 * NCTX, cnh, cnl, vh, vl, bkv + 512, nullptr,
        NCTX, NCTX, NCTX, NS,
        0L, (long)NS * NCTX, (long)ND * NS);

    // --- Q proj: q[p][c] = xn @ wq^T + bq  (hi only) ---
    gemm_fp16<1,0><<<dim3(NHW / 128, ND / 128, NB), 256, GSM>>>(
        xnh, wqh, wql, qh, nullptr, bq, nullptr,
        ND, ND, ND, ND,
        (long)NHW * ND, 0L, (long)NHW * ND);

    // --- sim + softmax -> P (fused) ---
    sim_softmax_k<<<dim3(NHW / 128, NB), 512, SSM>>>(qh, kh, kl, qscale);

    // --- PV: ao[p][c] = P @ v^T  (v stored [c][s]; hi/lo out) ---
    gemm_fp16<1,1><<<dim3(NHW / 128, ND / 128, NB), 256, GSM>>>(
        Ph, vh, vl, aoh, aol, nullptr, nullptr,
        NS, NS, NS, ND,
        (long)NHW * NS, (long)ND * NS, (long)NHW * ND);

    // --- O proj (transposed): out[c][p] = wo @ ao^T + bo[c] + x[c][p] ---
    gemm_fp16<3,0><<<dim3(ND / 128, NHW / 128, NB), 256, GSM>>>(
        woh, aoh, aol, out, nullptr, bo, x,
        ND, ND, ND, NHW,
        0L, (long)NHW * ND, (long)ND * NHW);
}

// round 13
// speedup vs baseline: 4.2561x; 1.4870x over previous
#include <cuda_runtime.h>
#include <cuda_fp16.h>
#include <cstdint>

// ---------------------------------------------------------------------------
// CrossAttention, single-product fp16 GEMMs (legacy mma.sync, sm_103).
// All operands rounded to fp16; fp32 accumulate. Calibrated rel_err ~1e-4.
// sim -> softmax -> P fused (no fp32 sim round-trip).
// ---------------------------------------------------------------------------

constexpr int NB   = 16;
constexpr int ND   = 512;
constexpr int NHW  = 4096;
constexpr int NS   = 256;
constexpr int NCTX = 768;
constexpr int NCPG = 16;
#define EPSV 1e-5f

typedef __half h16;

// ---- scratch (device globals; allocation-free) ----
__device__ float g_sc[NB * ND];
__device__ float g_sh[NB * ND];
__device__ __align__(256) h16 g_xnh[(size_t)NB * NHW * ND];   // A of Qproj
__device__ __align__(256) h16 g_qh [(size_t)NB * NHW * ND];   // A of sim
__device__ __align__(256) h16 g_Ph [(size_t)NB * NHW * NS];   // A of PV
__device__ __align__(256) h16 g_aoh[(size_t)NB * NHW * ND];   // B of Oproj
__device__ __align__(256) h16 g_cnh[NB * NS * NCTX];          // A of Kproj / B of Vproj
__device__ __align__(256) h16 g_kh [NB * NS * ND];            // B of sim
__device__ __align__(256) h16 g_vh [NB * ND * NS];            // B of PV ([c][s])
__device__ __align__(256) h16 g_wqh [ND * ND];                // B of Qproj
__device__ __align__(256) h16 g_wkvh[1024 * NCTX];            // rows<512: B of Kproj; >=512: A of Vproj
__device__ __align__(256) h16 g_woh [ND * ND];                // A of Oproj

// ---------------------------------------------------------------------------
// GroupNorm stats -> per-(b,c) scale/shift
// ---------------------------------------------------------------------------
__global__ void gn_stats_k(const float* __restrict__ x,
                           const float* __restrict__ gw,
                           const float* __restrict__ gb)
{
    int bg = blockIdx.x;
    int b = bg >> 5, g = bg & 31;
    const float4* p4 = (const float4*)(x + (size_t)bg * (NCPG * NHW));
    float s = 0.f, s2 = 0.f;
    const int n4 = NCPG * NHW / 4;
    for (int i = threadIdx.x; i < n4; i += 256) {
        float4 v = p4[i];
        s  += v.x + v.y + v.z + v.w;
        s2 += v.x*v.x + v.y*v.y + v.z*v.z + v.w*v.w;
    }
    #pragma unroll
    for (int o = 16; o > 0; o >>= 1) {
        s  += __shfl_down_sync(0xffffffffu, s,  o);
        s2 += __shfl_down_sync(0xffffffffu, s2, o);
    }
    __shared__ float shs[8], shs2[8];
    int lane = threadIdx.x & 31, w = threadIdx.x >> 5;
    if (lane == 0) { shs[w] = s; shs2[w] = s2; }
    __syncthreads();
    __shared__ float mm, rr;
    if (threadIdx.x == 0) {
        float ts = 0.f, ts2 = 0.f;
        #pragma unroll
        for (int i = 0; i < 8; i++) { ts += shs[i]; ts2 += shs2[i]; }
        float inv_n = 1.f / (float)(NCPG * NHW);
        float mean = ts * inv_n;
        float var  = ts2 * inv_n - mean * mean;
        mm = mean; rr = rsqrtf(var + EPSV);
    }
    __syncthreads();
    if (threadIdx.x < NCPG) {
        int ch = g * NCPG + threadIdx.x;
        float wv = gw[ch], bv = gb[ch];
        g_sc[b * ND + ch] = rr * wv;
        g_sh[b * ND + ch] = bv - mm * rr * wv;
    }
}

// ---------------------------------------------------------------------------
// x [b][c][p] --(GN affine + transpose)--> xn fp16 [b][p][c]
// ---------------------------------------------------------------------------
__global__ void xn_conv_k(const float* __restrict__ x)
{
    __shared__ float t[32][33];
    int b = blockIdx.z, p0 = blockIdx.x * 32, c0 = blockIdx.y * 32;
    int tx = threadIdx.x, ty = threadIdx.y;
    const float* xb = x + (size_t)b * ND * NHW;
    #pragma unroll
    for (int r = 0; r < 4; r++) {
        int c = c0 + ty + 8 * r;
        t[ty + 8 * r][tx] = xb[(size_t)c * NHW + p0 + tx] * g_sc[b * ND + c] + g_sh[b * ND + c];
    }
    __syncthreads();
    #pragma unroll
    for (int r = 0; r < 4; r++) {
        int p = p0 + ty + 8 * r;
        int c = c0 + tx;
        size_t o = ((size_t)b * NHW + p) * ND + c;
        g_xnh[o] = __float2half_rn(t[tx][ty + 8 * r]);
    }
}

// ---------------------------------------------------------------------------
// LayerNorm on context rows -> cn fp16
// ---------------------------------------------------------------------------
__global__ void ln_k(const float* __restrict__ ctx,
                     const float* __restrict__ lw,
                     const float* __restrict__ lb)
{
    int row = blockIdx.x;
    const float* p = ctx + (size_t)row * NCTX;
    float v[3];
    float s = 0.f, s2 = 0.f;
    #pragma unroll
    for (int r = 0; r < 3; r++) {
        v[r] = p[threadIdx.x + r * 256];
        s += v[r]; s2 += v[r] * v[r];
    }
    #pragma unroll
    for (int o = 16; o > 0; o >>= 1) {
        s  += __shfl_down_sync(0xffffffffu, s,  o);
        s2 += __shfl_down_sync(0xffffffffu, s2, o);
    }
    __shared__ float shs[8], shs2[8];
    int lane = threadIdx.x & 31, w = threadIdx.x >> 5;
    if (lane == 0) { shs[w] = s; shs2[w] = s2; }
    __syncthreads();
    __shared__ float mm, rr;
    if (threadIdx.x == 0) {
        float ts = 0.f, ts2 = 0.f;
        #pragma unroll
        for (int i = 0; i < 8; i++) { ts += shs[i]; ts2 += shs2[i]; }
        float inv_n = 1.f / (float)NCTX;
        float mean = ts * inv_n;
        float var  = ts2 * inv_n - mean * mean;
        mm = mean; rr = rsqrtf(var + EPSV);
    }
    __syncthreads();
    #pragma unroll
    for (int r = 0; r < 3; r++) {
        int i = threadIdx.x + r * 256;
        float val = (v[r] - mm) * rr * lw[i] + lb[i];
        g_cnh[(size_t)row * NCTX + i] = __float2half_rn(val);
    }
}

// ---------------------------------------------------------------------------
// weights fp32 -> fp16
// ---------------------------------------------------------------------------
__global__ void convw1_k(const float* __restrict__ w, h16* __restrict__ hi, int n)
{
    int i = blockIdx.x * 1024 + threadIdx.x * 4;
    if (i < n) {
        float4 v = *(const float4*)(w + i);
        __half2 a = __floats2half2_rn(v.x, v.y);
        __half2 b = __floats2half2_rn(v.z, v.w);
        *(__half2*)(hi + i)     = a;
        *(__half2*)(hi + i + 2) = b;
    }
}

// ---------------------------------------------------------------------------
// PTX helpers
// ---------------------------------------------------------------------------
__device__ __forceinline__ uint32_t smem_u32(const void* p) {
    uint32_t a;
    asm("{.reg .u64 t; cvta.to.shared.u64 t, %1; cvt.u32.u64 %0, t;}" : "=r"(a) : "l"(p));
    return a;
}
__device__ __forceinline__ void mma16816(float* d, const uint32_t* a, const uint32_t* b)
{
    asm volatile(
        "mma.sync.aligned.m16n8k16.row.col.f32.f16.f16.f32 "
        "{%0,%1,%2,%3},{%4,%5,%6,%7},{%8,%9},{%0,%1,%2,%3};"
        : "+f"(d[0]), "+f"(d[1]), "+f"(d[2]), "+f"(d[3])
        : "r"(a[0]), "r"(a[1]), "r"(a[2]), "r"(a[3]), "r"(b[0]), "r"(b[1]));
}
__device__ __forceinline__ void ldsm4(uint32_t& r0, uint32_t& r1, uint32_t& r2,
                                      uint32_t& r3, uint32_t addr)
{
    asm volatile("ldmatrix.sync.aligned.m8n8.x4.shared.b16 {%0,%1,%2,%3},[%4];"
        : "=r"(r0), "=r"(r1), "=r"(r2), "=r"(r3) : "r"(addr));
}
__device__ __forceinline__ void cpa16(uint32_t saddr, const void* gaddr)
{
    asm volatile("cp.async.cg.shared.global [%0],[%1],16;" :: "r"(saddr), "l"(gaddr));
}
#define CP_COMMIT() asm volatile("cp.async.commit_group;" ::: "memory")

// ---------------------------------------------------------------------------
// fp16 single-product GEMM: C[M,N] = A(MxK)*B(KxN)
// A [m][k] fp16, B [n][k] fp16 (k contiguous).
// Block 128x128, BK=16, 256 threads (8 warps, warp tile 64x32), 3-stage cp.async.
// EPI 1: fp16 C[m*ldc+n] = acc (+bias[n])
// EPI 2: fp16 C = acc + bias[m]
// EPI 3: fp32 C = acc + bias[m] + resid[m*ldc+n]
// ---------------------------------------------------------------------------
constexpr int PLA  = 128 * 12 * 4;   // 6144 B per plane (128 rows x 12 words)
constexpr int GST  = 2 * PLA;        // 12288 per stage (A, B)
constexpr int GSM  = 3 * GST;        // 36864 total

template<int EPI>
__global__ __launch_bounds__(256, 2)
void gemm_fp16(const h16* __restrict__ Ah, const h16* __restrict__ Bh,
               void* __restrict__ C0,
               const float* __restrict__ bias, const float* __restrict__ resid,
               int K, int lda, int ldb, int ldc,
               long sA, long sB, long sC)
{
    extern __shared__ __align__(16) char dsm[];
    const uint32_t sbase = smem_u32(dsm);
    const int tid = threadIdx.x, lane = tid & 31, wid = tid >> 5;
    const int bz = blockIdx.z;
    const int m0 = blockIdx.x * 128;
    const int n0 = blockIdx.y * 128;

    const h16* Ap = Ah + (size_t)bz * sA;
    const h16* Bp = Bh + (size_t)bz * sB;
    const int nIter = K >> 4;

    const int lrow = tid >> 1, lch = tid & 1;
    const uint32_t so = (uint32_t)((lrow * 12 + lch * 4) * 4);
    const size_t gAo = (size_t)(m0 + lrow) * lda + lch * 8;
    const size_t gBo = (size_t)(n0 + lrow) * ldb + lch * 8;

    auto issue = [&](int s) {
        int k0 = s << 4;
        uint32_t st = sbase + (s % 3) * GST;
        cpa16(st + so,       Ap + gAo + k0);
        cpa16(st + PLA + so, Bp + gBo + k0);
        CP_COMMIT();
    };

    const int mw = (wid & 1) * 64, nw = (wid >> 1) * 32;
    const int lr = lane & 7;
    const uint32_t aoff = (uint32_t)(((mw + lr + 8 * ((lane >> 3) & 1)) * 12
                                      + (lane >> 4) * 4) * 4);
    const uint32_t boff = (uint32_t)(((nw + 8 * (lane >> 4) + lr) * 12
                                      + ((lane >> 3) & 1) * 4) * 4);
    const int g = lane >> 2, tg = lane & 3;

    float acc[4][4][4];
    #pragma unroll
    for (int i = 0; i < 4; i++)
        #pragma unroll
        for (int j = 0; j < 4; j++)
            #pragma unroll
            for (int q = 0; q < 4; q++) acc[i][j][q] = 0.f;

    issue(0); issue(1);

    for (int it = 0; it < nIter; it++) {
        if (it + 1 < nIter) asm volatile("cp.async.wait_group 1;" ::: "memory");
        else                asm volatile("cp.async.wait_group 0;" ::: "memory");
        __syncthreads();
        if (it + 2 < nIter) issue(it + 2);

        uint32_t st = sbase + (it % 3) * GST;
        uint32_t aP = st, bP = st + PLA;

        uint32_t af[4][4], bh[4][2];
        ldsm4(bh[0][0], bh[0][1], bh[1][0], bh[1][1], bP + boff);
        ldsm4(bh[2][0], bh[2][1], bh[3][0], bh[3][1], bP + boff + 768);
        #pragma unroll
        for (int i = 0; i < 4; i++)
            ldsm4(af[i][0], af[i][1], af[i][2], af[i][3], aP + aoff + i * 768);
        #pragma unroll
        for (int i = 0; i < 4; i++)
            #pragma unroll
            for (int j = 0; j < 4; j++)
                mma16816(acc[i][j], af[i], bh[j]);
    }

    // ------------- epilogue -------------
    if constexpr (EPI == 1 || EPI == 2) {
        h16* Ch = (h16*)C0 + (size_t)bz * sC;
        #pragma unroll
        for (int i = 0; i < 4; i++) {
            int r = m0 + mw + 16 * i + g;
            #pragma unroll
            for (int j = 0; j < 4; j++) {
                int c = n0 + nw + 8 * j + 2 * tg;
                float b0, b1, b2, b3;
                if constexpr (EPI == 1) {
                    b0 = bias ? bias[c] : 0.f; b1 = bias ? bias[c + 1] : 0.f;
                    b2 = b0; b3 = b1;
                } else {
                    b0 = b1 = bias[r]; b2 = b3 = bias[r + 8];
                }
                *(__half2*)(Ch + (size_t)r * ldc + c) =
                    __floats2half2_rn(acc[i][j][0] + b0, acc[i][j][1] + b1);
                *(__half2*)(Ch + (size_t)(r + 8) * ldc + c) =
                    __floats2half2_rn(acc[i][j][2] + b2, acc[i][j][3] + b3);
            }
        }
    } else { // EPI == 3 : fp32 out + bias[m] + residual
        float* Co = (float*)C0 + (size_t)bz * sC;
        const float* R = resid + (size_t)bz * sC;
        #pragma unroll
        for (int i = 0; i < 4; i++) {
            int r = m0 + mw + 16 * i + g;
            float bv0 = bias[r], bv1 = bias[r + 8];
            #pragma unroll
            for (int j = 0; j < 4; j++) {
                int c = n0 + nw + 8 * j + 2 * tg;
                float2 rv0 = *(const float2*)(R + (size_t)r * ldc + c);
                float2 rv1 = *(const float2*)(R + (size_t)(r + 8) * ldc + c);
                float2 v0 = make_float2(acc[i][j][0] + bv0 + rv0.x,
                                        acc[i][j][1] + bv0 + rv0.y);
                float2 v1 = make_float2(acc[i][j][2] + bv1 + rv1.x,
                                        acc[i][j][3] + bv1 + rv1.y);
                *(float2*)(Co + (size_t)r * ldc + c)       = v0;
                *(float2*)(Co + (size_t)(r + 8) * ldc + c) = v1;
            }
        }
    }
}

// ---------------------------------------------------------------------------
// Fused sim -> softmax -> P (fp16).  Tile: 128 queries x full S=256 keys.
// 512 threads (16 warps: 2 m-warps x 8 n-warps, warp tile 64x32), K=512.
// ---------------------------------------------------------------------------
constexpr int SPA  = 128 * 12 * 4;     // 6144 (q plane)
constexpr int SPB  = 256 * 12 * 4;     // 12288 (k plane)
constexpr int SST  = SPA + SPB;        // 18432 per stage
constexpr int SRED = 3 * SST;          // 55296
constexpr int SSM  = SRED + 2 * 4608;  // + redM/redS (128x9 fp32 each) = 64512

__global__ __launch_bounds__(512, 1)
void sim_softmax_k(const h16* __restrict__ qh, const h16* __restrict__ kh,
                   float qscale)
{
    extern __shared__ __align__(16) char dsm[];
    const uint32_t sbase = smem_u32(dsm);
    float* redM = (float*)(dsm + SRED);
    float* redS = (float*)(dsm + SRED + 4608);
    const int tid = threadIdx.x, lane = tid & 31, wid = tid >> 5;
    const int b = blockIdx.y, p0 = blockIdx.x * 128;

    const h16* Qp = qh + (size_t)b * NHW * ND;
    const h16* Kp = kh + (size_t)b * NS * ND;

    const int lrow = tid >> 1, lch = tid & 1;
    const uint32_t so = (uint32_t)((lrow * 12 + lch * 4) * 4);

    auto issue = [&](int s) {
        int k0 = s << 4;
        uint32_t st = sbase + (s % 3) * SST;
        if (tid < 256)
            cpa16(st + so, Qp + (size_t)(p0 + lrow) * ND + k0 + lch * 8);
        cpa16(st + SPA + so, Kp + (size_t)lrow * ND + k0 + lch * 8);
        CP_COMMIT();
    };

    const int mwp = wid & 1, nwp = wid >> 1;
    const int mw = mwp * 64, nw = nwp * 32;
    const int lr = lane & 7;
    const uint32_t aoff = (uint32_t)(((mw + lr + 8 * ((lane >> 3) & 1)) * 12
                                      + (lane >> 4) * 4) * 4);
    const uint32_t boff = (uint32_t)(((nw + 8 * (lane >> 4) + lr) * 12
                                      + ((lane >> 3) & 1) * 4) * 4);
    const int g = lane >> 2, tg = lane & 3;

    float acc[4][4][4];
    #pragma unroll
    for (int i = 0; i < 4; i++)
        #pragma unroll
        for (int j = 0; j < 4; j++)
            #pragma unroll
            for (int q = 0; q < 4; q++) acc[i][j][q] = 0.f;

    const int nIter = ND >> 4;   // 32
    issue(0); issue(1);

    for (int it = 0; it < nIter; it++) {
        if (it + 1 < nIter) asm volatile("cp.async.wait_group 1;" ::: "memory");
        else                asm volatile("cp.async.wait_group 0;" ::: "memory");
        __syncthreads();
        if (it + 2 < nIter) issue(it + 2);

        uint32_t st = sbase + (it % 3) * SST;
        uint32_t aP = st, bP = st + SPA;

        uint32_t af[4][4], bh[4][2];
        ldsm4(bh[0][0], bh[0][1], bh[1][0], bh[1][1], bP + boff);
        ldsm4(bh[2][0], bh[2][1], bh[3][0], bh[3][1], bP + boff + 768);
        #pragma unroll
        for (int i = 0; i < 4; i++)
            ldsm4(af[i][0], af[i][1], af[i][2], af[i][3], aP + aoff + i * 768);
        #pragma unroll
        for (int i = 0; i < 4; i++)
            #pragma unroll
            for (int j = 0; j < 4; j++)
                mma16816(acc[i][j], af[i], bh[j]);
    }

    // ---- scale ----
    #pragma unroll
    for (int i = 0; i < 4; i++)
        #pragma unroll
        for (int j = 0; j < 4; j++)
            #pragma unroll
            for (int q = 0; q < 4; q++) acc[i][j][q] *= qscale;

    // ---- row max ----
    float rmx[4][2];
    #pragma unroll
    for (int i = 0; i < 4; i++)
        #pragma unroll
        for (int h = 0; h < 2; h++) {
            float m = -1e30f;
            #pragma unroll
            for (int j = 0; j < 4; j++)
                m = fmaxf(m, fmaxf(acc[i][j][2 * h], acc[i][j][2 * h + 1]));
            rmx[i][h] = m;
        }
    #pragma unroll
    for (int o = 1; o <= 2; o <<= 1)
        #pragma unroll
        for (int i = 0; i < 4; i++)
            #pragma unroll
            for (int h = 0; h < 2; h++)
                rmx[i][h] = fmaxf(rmx[i][h], __shfl_xor_sync(0xffffffffu, rmx[i][h], o));
    if (tg == 0) {
        #pragma unroll
        for (int i = 0; i < 4; i++)
            #pragma unroll
            for (int h = 0; h < 2; h++)
                redM[(mw + 16 * i + 8 * h + g) * 9 + nwp] = rmx[i][h];
    }
    __syncthreads();
    float rM[4][2];
    #pragma unroll
    for (int i = 0; i < 4; i++)
        #pragma unroll
        for (int h = 0; h < 2; h++) {
            int R = mw + 16 * i + 8 * h + g;
            float m = -1e30f;
            #pragma unroll
            for (int w = 0; w < 8; w++) m = fmaxf(m, redM[R * 9 + w]);
            rM[i][h] = m;
        }

    // ---- exp + row sum ----
    float rsm[4][2] = {{0.f,0.f},{0.f,0.f},{0.f,0.f},{0.f,0.f}};
    #pragma unroll
    for (int i = 0; i < 4; i++)
        #pragma unroll
        for (int j = 0; j < 4; j++)
            #pragma unroll
            for (int h = 0; h < 2; h++) {
                float e0 = __expf(acc[i][j][2*h]     - rM[i][h]);
                float e1 = __expf(acc[i][j][2*h + 1] - rM[i][h]);
                acc[i][j][2*h]     = e0;
                acc[i][j][2*h + 1] = e1;
                rsm[i][h] += e0 + e1;
            }
    #pragma unroll
    for (int o = 1; o <= 2; o <<= 1)
        #pragma unroll
        for (int i = 0; i < 4; i++)
            #pragma unroll
            for (int h = 0; h < 2; h++)
                rsm[i][h] += __shfl_xor_sync(0xffffffffu, rsm[i][h], o);
    if (tg == 0) {
        #pragma unroll
        for (int i = 0; i < 4; i++)
            #pragma unroll
            for (int h = 0; h < 2; h++)
                redS[(mw + 16 * i + 8 * h + g) * 9 + nwp] = rsm[i][h];
    }
    __syncthreads();

    h16* Pp = g_Ph + ((size_t)b * NHW + p0) * NS;
    #pragma unroll
    for (int i = 0; i < 4; i++)
        #pragma unroll
        for (int h = 0; h < 2; h++) {
            int R = mw + 16 * i + 8 * h + g;
            float sum = 0.f;
            #pragma unroll
            for (int w = 0; w < 8; w++) sum += redS[R * 9 + w];
            float inv = 1.f / sum;
            #pragma unroll
            for (int j = 0; j < 4; j++) {
                int c = nw + 8 * j + 2 * tg;
                *(__half2*)(Pp + (size_t)R * NS + c) =
                    __floats2half2_rn(acc[i][j][2*h] * inv, acc[i][j][2*h + 1] * inv);
            }
        }
}

// ---------------------------------------------------------------------------
extern "C" void kernel_launch(void* const* d_in, const int* in_sizes, int n_in,
                              void* d_out, int out_size)
{
    const float* x    = (const float*)d_in[0];
    const float* ctx  = (const float*)d_in[1];
    const float* gn_w = (const float*)d_in[2];
    const float* gn_b = (const float*)d_in[3];
    const float* ln_w = (const float*)d_in[4];
    const float* ln_b = (const float*)d_in[5];
    const float* wq   = (const float*)d_in[6];
    const float* bq   = (const float*)d_in[7];
    const float* wkv  = (const float*)d_in[8];
    const float* bkv  = (const float*)d_in[9];
    const float* wo   = (const float*)d_in[10];
    const float* bo   = (const float*)d_in[11];
    float* out = (float*)d_out;

    cudaFuncSetAttribute(gemm_fp16<1>, cudaFuncAttributeMaxDynamicSharedMemorySize, GSM);
    cudaFuncSetAttribute(gemm_fp16<2>, cudaFuncAttributeMaxDynamicSharedMemorySize, GSM);
    cudaFuncSetAttribute(gemm_fp16<3>, cudaFuncAttributeMaxDynamicSharedMemorySize, GSM);
    cudaFuncSetAttribute(sim_softmax_k, cudaFuncAttributeMaxDynamicSharedMemorySize, SSM);

    h16 *xnh, *qh, *Ph, *aoh, *cnh, *kh, *vh, *wqh, *wkvh, *woh;
    cudaGetSymbolAddress((void**)&xnh, g_xnh);
    cudaGetSymbolAddress((void**)&qh,  g_qh);
    cudaGetSymbolAddress((void**)&Ph,  g_Ph);
    cudaGetSymbolAddress((void**)&aoh, g_aoh);
    cudaGetSymbolAddress((void**)&cnh, g_cnh);
    cudaGetSymbolAddress((void**)&kh,  g_kh);
    cudaGetSymbolAddress((void**)&vh,  g_vh);
    cudaGetSymbolAddress((void**)&wqh, g_wqh);
    cudaGetSymbolAddress((void**)&wkvh, g_wkvh);
    cudaGetSymbolAddress((void**)&woh, g_woh);

    const float qscale = 0.044194173824159216f; // 512^-0.5

    // --- prep ---
    gn_stats_k<<<NB * 32, 256>>>(x, gn_w, gn_b);
    ln_k<<<NB * NS, 256>>>(ctx, ln_w, ln_b);
    convw1_k<<<(ND * ND + 1023) / 1024, 256>>>(wq, wqh, ND * ND);
    convw1_k<<<(1024 * NCTX + 1023) / 1024, 256>>>(wkv, wkvh, 1024 * NCTX);
    convw1_k<<<(ND * ND + 1023) / 1024, 256>>>(wo, woh, ND * ND);
    xn_conv_k<<<dim3(NHW / 32, ND / 32, NB), dim3(32, 8)>>>(x);

    // --- K proj: k[s][c] = cn @ wkv[0:512]^T + bkv[0:512] ---
    gemm_fp16<1><<<dim3(NS / 128, ND / 128, NB), 256, GSM>>>(
        cnh, wkvh, kh, bkv, nullptr,
        NCTX, NCTX, NCTX, ND,
        (long)NS * NCTX, 0L, (long)NS * ND);

    // --- V proj (transposed): v[c][s] = wkv[512:] @ cn^T + bkv[512+c] ---
    gemm_fp16<2><<<dim3(ND / 128, NS / 128, NB), 256, GSM>>>(
        wkvh + (size_t)512 * NCTX, cnh, vh, bkv + 512, nullptr,
        NCTX, NCTX, NCTX, NS,
        0L, (long)NS * NCTX, (long)ND * NS);

    // --- Q proj: q[p][c] = xn @ wq^T + bq ---
    gemm_fp16<1><<<dim3(NHW / 128, ND / 128, NB), 256, GSM>>>(
        xnh, wqh, qh, bq, nullptr,
        ND, ND, ND, ND,
        (long)NHW * ND, 0L, (long)NHW * ND);

    // --- sim + softmax -> P (fused) ---
    sim_softmax_k<<<dim3(NHW / 128, NB), 512, SSM>>>(qh, kh, qscale);

    // --- PV: ao[p][c] = P @ v^T  (v stored [c][s]) ---
    gemm_fp16<1><<<dim3(NHW / 128, ND / 128, NB), 256, GSM>>>(
        Ph, vh, aoh, nullptr, nullptr,
        NS, NS, NS, ND,
        (long)NHW * NS, (long)ND * NS, (long)NHW * ND);

    // --- O proj (transposed): out[c][p] = wo @ ao^T + bo[c] + x[c][p] ---
    gemm_fp16<3><<<dim3(ND / 128, NHW / 128, NB), 256, GSM>>>(
        woh, aoh, out, bo, x,
        ND, ND, ND, NHW,
        0L, (long)NHW * ND, (long)ND * NHW);
}

// round 14
// speedup vs baseline: 4.4916x; 1.0553x over previous
#include <cuda_runtime.h>
#include <cuda_fp16.h>
#include <cstdint>

// ---------------------------------------------------------------------------
// CrossAttention, single-product fp16 GEMMs (legacy mma.sync, sm_103).
// Multi-stream overlap of context path; sim+softmax+PV fused (P in smem).
// ---------------------------------------------------------------------------

constexpr int NB   = 16;
constexpr int ND   = 512;
constexpr int NHW  = 4096;
constexpr int NS   = 256;
constexpr int NCTX = 768;
constexpr int NCPG = 16;
#define EPSV 1e-5f

typedef __half h16;

// ---- scratch (device globals; allocation-free) ----
__device__ float g_sc[NB * ND];
__device__ float g_sh[NB * ND];
__device__ __align__(256) h16 g_xnh[(size_t)NB * NHW * ND];   // A of Qproj
__device__ __align__(256) h16 g_qh [(size_t)NB * NHW * ND];   // A of sim
__device__ __align__(256) h16 g_aoh[(size_t)NB * NHW * ND];   // B of Oproj
__device__ __align__(256) h16 g_cnh[NB * NS * NCTX];          // A of Kproj / B of Vproj
__device__ __align__(256) h16 g_kh [NB * NS * ND];            // B of sim
__device__ __align__(256) h16 g_vh [NB * ND * NS];            // B of PV ([c][s])
__device__ __align__(256) h16 g_wqh [ND * ND];
__device__ __align__(256) h16 g_wkvh[1024 * NCTX];
__device__ __align__(256) h16 g_woh [ND * ND];

// ---------------------------------------------------------------------------
// GroupNorm stats -> per-(b,c) scale/shift
// ---------------------------------------------------------------------------
__global__ void gn_stats_k(const float* __restrict__ x,
                           const float* __restrict__ gw,
                           const float* __restrict__ gb)
{
    int bg = blockIdx.x;
    int b = bg >> 5, g = bg & 31;
    const float4* p4 = (const float4*)(x + (size_t)bg * (NCPG * NHW));
    float s = 0.f, s2 = 0.f;
    const int n4 = NCPG * NHW / 4;
    for (int i = threadIdx.x; i < n4; i += 256) {
        float4 v = p4[i];
        s  += v.x + v.y + v.z + v.w;
        s2 += v.x*v.x + v.y*v.y + v.z*v.z + v.w*v.w;
    }
    #pragma unroll
    for (int o = 16; o > 0; o >>= 1) {
        s  += __shfl_down_sync(0xffffffffu, s,  o);
        s2 += __shfl_down_sync(0xffffffffu, s2, o);
    }
    __shared__ float shs[8], shs2[8];
    int lane = threadIdx.x & 31, w = threadIdx.x >> 5;
    if (lane == 0) { shs[w] = s; shs2[w] = s2; }
    __syncthreads();
    __shared__ float mm, rr;
    if (threadIdx.x == 0) {
        float ts = 0.f, ts2 = 0.f;
        #pragma unroll
        for (int i = 0; i < 8; i++) { ts += shs[i]; ts2 += shs2[i]; }
        float inv_n = 1.f / (float)(NCPG * NHW);
        float mean = ts * inv_n;
        float var  = ts2 * inv_n - mean * mean;
        mm = mean; rr = rsqrtf(var + EPSV);
    }
    __syncthreads();
    if (threadIdx.x < NCPG) {
        int ch = g * NCPG + threadIdx.x;
        float wv = gw[ch], bv = gb[ch];
        g_sc[b * ND + ch] = rr * wv;
        g_sh[b * ND + ch] = bv - mm * rr * wv;
    }
}

// ---------------------------------------------------------------------------
// x [b][c][p] --(GN affine + transpose)--> xn fp16 [b][p][c], half2 stores
// ---------------------------------------------------------------------------
__global__ void xn_conv_k(const float* __restrict__ x)
{
    __shared__ float t[32][33];
    int b = blockIdx.z, p0 = blockIdx.x * 32, c0 = blockIdx.y * 32;
    int tx = threadIdx.x, ty = threadIdx.y;
    const float* xb = x + (size_t)b * ND * NHW;
    #pragma unroll
    for (int r = 0; r < 4; r++) {
        int c = c0 + ty + 8 * r;
        t[ty + 8 * r][tx] = xb[(size_t)c * NHW + p0 + tx] * g_sc[b * ND + c] + g_sh[b * ND + c];
    }
    __syncthreads();
    int w  = ty * 32 + tx;        // 0..255
    int ci = (w & 15) * 2;
    int pr = w >> 4;              // 0..15
    #pragma unroll
    for (int r2 = 0; r2 < 2; r2++) {
        int pp = pr + 16 * r2;
        __half2 hv = __floats2half2_rn(t[ci][pp], t[ci + 1][pp]);
        *(__half2*)(g_xnh + ((size_t)b * NHW + p0 + pp) * ND + c0 + ci) = hv;
    }
}

// ---------------------------------------------------------------------------
// LayerNorm on context rows -> cn fp16
// ---------------------------------------------------------------------------
__global__ void ln_k(const float* __restrict__ ctx,
                     const float* __restrict__ lw,
                     const float* __restrict__ lb)
{
    int row = blockIdx.x;
    const float* p = ctx + (size_t)row * NCTX;
    float v[3];
    float s = 0.f, s2 = 0.f;
    #pragma unroll
    for (int r = 0; r < 3; r++) {
        v[r] = p[threadIdx.x + r * 256];
        s += v[r]; s2 += v[r] * v[r];
    }
    #pragma unroll
    for (int o = 16; o > 0; o >>= 1) {
        s  += __shfl_down_sync(0xffffffffu, s,  o);
        s2 += __shfl_down_sync(0xffffffffu, s2, o);
    }
    __shared__ float shs[8], shs2[8];
    int lane = threadIdx.x & 31, w = threadIdx.x >> 5;
    if (lane == 0) { shs[w] = s; shs2[w] = s2; }
    __syncthreads();
    __shared__ float mm, rr;
    if (threadIdx.x == 0) {
        float ts = 0.f, ts2 = 0.f;
        #pragma unroll
        for (int i = 0; i < 8; i++) { ts += shs[i]; ts2 += shs2[i]; }
        float inv_n = 1.f / (float)NCTX;
        float mean = ts * inv_n;
        float var  = ts2 * inv_n - mean * mean;
        mm = mean; rr = rsqrtf(var + EPSV);
    }
    __syncthreads();
    #pragma unroll
    for (int r = 0; r < 3; r++) {
        int i = threadIdx.x + r * 256;
        float val = (v[r] - mm) * rr * lw[i] + lb[i];
        g_cnh[(size_t)row * NCTX + i] = __float2half_rn(val);
    }
}

// ---------------------------------------------------------------------------
// weights fp32 -> fp16
// ---------------------------------------------------------------------------
__global__ void convw1_k(const float* __restrict__ w, h16* __restrict__ hi, int n)
{
    int i = blockIdx.x * 1024 + threadIdx.x * 4;
    if (i < n) {
        float4 v = *(const float4*)(w + i);
        *(__half2*)(hi + i)     = __floats2half2_rn(v.x, v.y);
        *(__half2*)(hi + i + 2) = __floats2half2_rn(v.z, v.w);
    }
}

// ---------------------------------------------------------------------------
// PTX helpers
// ---------------------------------------------------------------------------
__device__ __forceinline__ uint32_t smem_u32(const void* p) {
    uint32_t a;
    asm("{.reg .u64 t; cvta.to.shared.u64 t, %1; cvt.u32.u64 %0, t;}" : "=r"(a) : "l"(p));
    return a;
}
__device__ __forceinline__ void mma16816(float* d, const uint32_t* a, const uint32_t* b)
{
    asm volatile(
        "mma.sync.aligned.m16n8k16.row.col.f32.f16.f16.f32 "
        "{%0,%1,%2,%3},{%4,%5,%6,%7},{%8,%9},{%0,%1,%2,%3};"
        : "+f"(d[0]), "+f"(d[1]), "+f"(d[2]), "+f"(d[3])
        : "r"(a[0]), "r"(a[1]), "r"(a[2]), "r"(a[3]), "r"(b[0]), "r"(b[1]));
}
__device__ __forceinline__ void ldsm4(uint32_t& r0, uint32_t& r1, uint32_t& r2,
                                      uint32_t& r3, uint32_t addr)
{
    asm volatile("ldmatrix.sync.aligned.m8n8.x4.shared.b16 {%0,%1,%2,%3},[%4];"
        : "=r"(r0), "=r"(r1), "=r"(r2), "=r"(r3) : "r"(addr));
}
__device__ __forceinline__ void cpa16(uint32_t saddr, const void* gaddr)
{
    asm volatile("cp.async.cg.shared.global [%0],[%1],16;" :: "r"(saddr), "l"(gaddr));
}
#define CP_COMMIT() asm volatile("cp.async.commit_group;" ::: "memory")

// ---------------------------------------------------------------------------
// fp16 GEMM: C[M,N] = A(MxK)*B(KxN); A [m][k], B [n][k].
// Block 128x128, BK=16, 256 threads (8 warps, warp 64x32), 3-stage cp.async.
// EPI 1: fp16 C = acc (+bias[n]); EPI 2: fp16 C = acc + bias[m];
// EPI 3: fp32 C = acc + bias[m] + resid.
// ---------------------------------------------------------------------------
constexpr int PLA  = 128 * 12 * 4;
constexpr int GST  = 2 * PLA;
constexpr int GSM  = 3 * GST;

template<int EPI>
__global__ __launch_bounds__(256, 2)
void gemm_fp16(const h16* __restrict__ Ah, const h16* __restrict__ Bh,
               void* __restrict__ C0,
               const float* __restrict__ bias, const float* __restrict__ resid,
               int K, int lda, int ldb, int ldc,
               long sA, long sB, long sC)
{
    extern __shared__ __align__(16) char dsm[];
    const uint32_t sbase = smem_u32(dsm);
    const int tid = threadIdx.x, lane = tid & 31, wid = tid >> 5;
    const int bz = blockIdx.z;
    const int m0 = blockIdx.x * 128;
    const int n0 = blockIdx.y * 128;

    const h16* Ap = Ah + (size_t)bz * sA;
    const h16* Bp = Bh + (size_t)bz * sB;
    const int nIter = K >> 4;

    const int lrow = tid >> 1, lch = tid & 1;
    const uint32_t so = (uint32_t)((lrow * 12 + lch * 4) * 4);
    const size_t gAo = (size_t)(m0 + lrow) * lda + lch * 8;
    const size_t gBo = (size_t)(n0 + lrow) * ldb + lch * 8;

    auto issue = [&](int s) {
        int k0 = s << 4;
        uint32_t st = sbase + (s % 3) * GST;
        cpa16(st + so,       Ap + gAo + k0);
        cpa16(st + PLA + so, Bp + gBo + k0);
        CP_COMMIT();
    };

    const int mw = (wid & 1) * 64, nw = (wid >> 1) * 32;
    const int lr = lane & 7;
    const uint32_t aoff = (uint32_t)(((mw + lr + 8 * ((lane >> 3) & 1)) * 12
                                      + (lane >> 4) * 4) * 4);
    const uint32_t boff = (uint32_t)(((nw + 8 * (lane >> 4) + lr) * 12
                                      + ((lane >> 3) & 1) * 4) * 4);
    const int g = lane >> 2, tg = lane & 3;

    float acc[4][4][4];
    #pragma unroll
    for (int i = 0; i < 4; i++)
        #pragma unroll
        for (int j = 0; j < 4; j++)
            #pragma unroll
            for (int q = 0; q < 4; q++) acc[i][j][q] = 0.f;

    issue(0); issue(1);

    for (int it = 0; it < nIter; it++) {
        if (it + 1 < nIter) asm volatile("cp.async.wait_group 1;" ::: "memory");
        else                asm volatile("cp.async.wait_group 0;" ::: "memory");
        __syncthreads();
        if (it + 2 < nIter) issue(it + 2);

        uint32_t st = sbase + (it % 3) * GST;
        uint32_t af[4][4], bh[4][2];
        ldsm4(bh[0][0], bh[0][1], bh[1][0], bh[1][1], st + PLA + boff);
        ldsm4(bh[2][0], bh[2][1], bh[3][0], bh[3][1], st + PLA + boff + 768);
        #pragma unroll
        for (int i = 0; i < 4; i++)
            ldsm4(af[i][0], af[i][1], af[i][2], af[i][3], st + aoff + i * 768);
        #pragma unroll
        for (int i = 0; i < 4; i++)
            #pragma unroll
            for (int j = 0; j < 4; j++)
                mma16816(acc[i][j], af[i], bh[j]);
    }

    if constexpr (EPI == 1 || EPI == 2) {
        h16* Ch = (h16*)C0 + (size_t)bz * sC;
        #pragma unroll
        for (int i = 0; i < 4; i++) {
            int r = m0 + mw + 16 * i + g;
            #pragma unroll
            for (int j = 0; j < 4; j++) {
                int c = n0 + nw + 8 * j + 2 * tg;
                float b0, b1, b2, b3;
                if constexpr (EPI == 1) {
                    b0 = bias ? bias[c] : 0.f; b1 = bias ? bias[c + 1] : 0.f;
                    b2 = b0; b3 = b1;
                } else {
                    b0 = b1 = bias[r]; b2 = b3 = bias[r + 8];
                }
                *(__half2*)(Ch + (size_t)r * ldc + c) =
                    __floats2half2_rn(acc[i][j][0] + b0, acc[i][j][1] + b1);
                *(__half2*)(Ch + (size_t)(r + 8) * ldc + c) =
                    __floats2half2_rn(acc[i][j][2] + b2, acc[i][j][3] + b3);
            }
        }
    } else {
        float* Co = (float*)C0 + (size_t)bz * sC;
        const float* R = resid + (size_t)bz * sC;
        #pragma unroll
        for (int i = 0; i < 4; i++) {
            int r = m0 + mw + 16 * i + g;
            float bv0 = bias[r], bv1 = bias[r + 8];
            #pragma unroll
            for (int j = 0; j < 4; j++) {
                int c = n0 + nw + 8 * j + 2 * tg;
                float2 rv0 = *(const float2*)(R + (size_t)r * ldc + c);
                float2 rv1 = *(const float2*)(R + (size_t)(r + 8) * ldc + c);
                *(float2*)(Co + (size_t)r * ldc + c) =
                    make_float2(acc[i][j][0] + bv0 + rv0.x, acc[i][j][1] + bv0 + rv0.y);
                *(float2*)(Co + (size_t)(r + 8) * ldc + c) =
                    make_float2(acc[i][j][2] + bv1 + rv1.x, acc[i][j][3] + bv1 + rv1.y);
            }
        }
    }
}

// ---------------------------------------------------------------------------
// Fused sim -> softmax -> PV.  Tile: 128 queries x S=256 x full out D=512.
// 512 threads (16 warps: 2 m x 8 n). P kept in smem (swizzled 512B rows).
// ---------------------------------------------------------------------------
constexpr int ASPA = 128 * 12 * 4;        // 6144  (q plane)
constexpr int ASPB = 256 * 12 * 4;        // 12288 (k/v plane)
constexpr int ASST = ASPA + ASPB;         // 18432 per stage
constexpr int APOFF = 3 * ASST;           // 55296 (P tile, 64KB)
constexpr int ARM  = APOFF + 65536;       // 120832
constexpr int ARS  = ARM + 4608;          // 125440
constexpr int ASM  = ARS + 4608;          // 130048

__global__ __launch_bounds__(512)
void attn_k(const h16* __restrict__ qh, const h16* __restrict__ kh,
            const h16* __restrict__ vh, float qscale)
{
    extern __shared__ __align__(16) char dsm[];
    const uint32_t sbase = smem_u32(dsm);
    float* redM = (float*)(dsm + ARM);
    float* redS = (float*)(dsm + ARS);
    const int tid = threadIdx.x, lane = tid & 31, wid = tid >> 5;
    const int b = blockIdx.y, p0 = blockIdx.x * 128;

    const h16* Qp = qh + (size_t)b * NHW * ND;
    const h16* Kp = kh + (size_t)b * NS * ND;
    const h16* Vp = vh + (size_t)b * ND * NS;

    const int lrow = tid >> 1, lch = tid & 1;
    const uint32_t so = (uint32_t)((lrow * 12 + lch * 4) * 4);

    const int mwp = wid & 1, nwp = wid >> 1;
    const int mw = mwp * 64, nw = nwp * 32;
    const int lr = lane & 7;
    const uint32_t aoff = (uint32_t)(((mw + lr + 8 * ((lane >> 3) & 1)) * 12
                                      + (lane >> 4) * 4) * 4);
    const uint32_t boff = (uint32_t)(((nw + 8 * (lane >> 4) + lr) * 12
                                      + ((lane >> 3) & 1) * 4) * 4);
    const int g = lane >> 2, tg = lane & 3;

    float acc[4][4][4];
    #pragma unroll
    for (int i = 0; i < 4; i++)
        #pragma unroll
        for (int j = 0; j < 4; j++)
            #pragma unroll
            for (int q = 0; q < 4; q++) acc[i][j][q] = 0.f;

    // ---------------- phase 1: sim = q @ k^T ----------------
    auto issueQK = [&](int s) {
        int k0 = s << 4;
        uint32_t st = sbase + (s % 3) * ASST;
        if (tid < 256)
            cpa16(st + so, Qp + (size_t)(p0 + lrow) * ND + k0 + lch * 8);
        cpa16(st + ASPA + so, Kp + (size_t)lrow * ND + k0 + lch * 8);
        CP_COMMIT();
    };
    issueQK(0); issueQK(1);
    const int nI1 = ND >> 4;   // 32
    for (int it = 0; it < nI1; it++) {
        if (it + 1 < nI1) asm volatile("cp.async.wait_group 1;" ::: "memory");
        else              asm volatile("cp.async.wait_group 0;" ::: "memory");
        __syncthreads();
        if (it + 2 < nI1) issueQK(it + 2);

        uint32_t st = sbase + (it % 3) * ASST;
        uint32_t af[4][4], bh[4][2];
        ldsm4(bh[0][0], bh[0][1], bh[1][0], bh[1][1], st + ASPA + boff);
        ldsm4(bh[2][0], bh[2][1], bh[3][0], bh[3][1], st + ASPA + boff + 768);
        #pragma unroll
        for (int i = 0; i < 4; i++)
            ldsm4(af[i][0], af[i][1], af[i][2], af[i][3], st + aoff + i * 768);
        #pragma unroll
        for (int i = 0; i < 4; i++)
            #pragma unroll
            for (int j = 0; j < 4; j++)
                mma16816(acc[i][j], af[i], bh[j]);
    }

    // ---------------- softmax ----------------
    #pragma unroll
    for (int i = 0; i < 4; i++)
        #pragma unroll
        for (int j = 0; j < 4; j++)
            #pragma unroll
            for (int q = 0; q < 4; q++) acc[i][j][q] *= qscale;

    float rmx[4][2];
    #pragma unroll
    for (int i = 0; i < 4; i++)
        #pragma unroll
        for (int h = 0; h < 2; h++) {
            float m = -1e30f;
            #pragma unroll
            for (int j = 0; j < 4; j++)
                m = fmaxf(m, fmaxf(acc[i][j][2 * h], acc[i][j][2 * h + 1]));
            rmx[i][h] = m;
        }
    #pragma unroll
    for (int o = 1; o <= 2; o <<= 1)
        #pragma unroll
        for (int i = 0; i < 4; i++)
            #pragma unroll
            for (int h = 0; h < 2; h++)
                rmx[i][h] = fmaxf(rmx[i][h], __shfl_xor_sync(0xffffffffu, rmx[i][h], o));
    if (tg == 0) {
        #pragma unroll
        for (int i = 0; i < 4; i++)
            #pragma unroll
            for (int h = 0; h < 2; h++)
                redM[(mw + 16 * i + 8 * h + g) * 9 + nwp] = rmx[i][h];
    }
    __syncthreads();
    float rM[4][2];
    #pragma unroll
    for (int i = 0; i < 4; i++)
        #pragma unroll
        for (int h = 0; h < 2; h++) {
            int R = mw + 16 * i + 8 * h + g;
            float m = -1e30f;
            #pragma unroll
            for (int w = 0; w < 8; w++) m = fmaxf(m, redM[R * 9 + w]);
            rM[i][h] = m;
        }

    float rsm[4][2] = {{0.f,0.f},{0.f,0.f},{0.f,0.f},{0.f,0.f}};
    #pragma unroll
    for (int i = 0; i < 4; i++)
        #pragma unroll
        for (int j = 0; j < 4; j++)
            #pragma unroll
            for (int h = 0; h < 2; h++) {
                float e0 = __expf(acc[i][j][2*h]     - rM[i][h]);
                float e1 = __expf(acc[i][j][2*h + 1] - rM[i][h]);
                acc[i][j][2*h]     = e0;
                acc[i][j][2*h + 1] = e1;
                rsm[i][h] += e0 + e1;
            }
    #pragma unroll
    for (int o = 1; o <= 2; o <<= 1)
        #pragma unroll
        for (int i = 0; i < 4; i++)
            #pragma unroll
            for (int h = 0; h < 2; h++)
                rsm[i][h] += __shfl_xor_sync(0xffffffffu, rsm[i][h], o);
    if (tg == 0) {
        #pragma unroll
        for (int i = 0; i < 4; i++)
            #pragma unroll
            for (int h = 0; h < 2; h++)
                redS[(mw + 16 * i + 8 * h + g) * 9 + nwp] = rsm[i][h];
    }
    __syncthreads();

    // write P to smem (swizzled: unit u of row R at ((u ^ (R&7)) * 16))
    #pragma unroll
    for (int i = 0; i < 4; i++)
        #pragma unroll
        for (int h = 0; h < 2; h++) {
            int R = mw + 16 * i + 8 * h + g;
            float sum = 0.f;
            #pragma unroll
            for (int w = 0; w < 8; w++) sum += redS[R * 9 + w];
            float inv = 1.f / sum;
            #pragma unroll
            for (int j = 0; j < 4; j++) {
                int c = nw + 8 * j + 2 * tg;
                int u = c >> 3;
                char* pa = dsm + APOFF + R * 512 + ((u ^ (R & 7)) << 4) + (c & 7) * 2;
                *(__half2*)pa = __floats2half2_rn(acc[i][j][2*h] * inv,
                                                  acc[i][j][2*h + 1] * inv);
            }
        }
    __syncthreads();

    // ---------------- phase 2: PV = P @ v^T ----------------
    const uint32_t Pb = sbase + APOFF;
    const int arow = mw + (lane & 15);
    const uint32_t swz = (uint32_t)(arow & 7);
    const uint32_t uo = (uint32_t)(lane >> 4);
    uint32_t rowA[4];
    #pragma unroll
    for (int i = 0; i < 4; i++) rowA[i] = Pb + (arow + 16 * i) * 512;

    h16* Cp = g_aoh + ((size_t)b * NHW + p0) * ND;

    #pragma unroll 1
    for (int nc = 0; nc < 2; nc++) {
        #pragma unroll
        for (int i = 0; i < 4; i++)
            #pragma unroll
            for (int j = 0; j < 4; j++)
                #pragma unroll
                for (int q = 0; q < 4; q++) acc[i][j][q] = 0.f;

        auto issueV = [&](int s) {
            int s0 = s << 4;
            uint32_t st = sbase + (s % 3) * ASST;
            cpa16(st + so, Vp + (size_t)(nc * 256 + lrow) * NS + s0 + lch * 8);
            CP_COMMIT();
        };
        issueV(0); issueV(1);
        const int nI2 = NS >> 4;   // 16
        for (int it = 0; it < nI2; it++) {
            if (it + 1 < nI2) asm volatile("cp.async.wait_group 1;" ::: "memory");
            else              asm volatile("cp.async.wait_group 0;" ::: "memory");
            __syncthreads();
            if (it + 2 < nI2) issueV(it + 2);

            uint32_t st = sbase + (it % 3) * ASST;
            uint32_t af[4][4], bh[4][2];
            ldsm4(bh[0][0], bh[0][1], bh[1][0], bh[1][1], st + boff);
            ldsm4(bh[2][0], bh[2][1], bh[3][0], bh[3][1], st + boff + 768);
            #pragma unroll
            for (int i = 0; i < 4; i++) {
                uint32_t ua = ((2u * (uint32_t)it + uo) ^ swz) << 4;
                ldsm4(af[i][0], af[i][1], af[i][2], af[i][3], rowA[i] + ua);
            }
            #pragma unroll
            for (int i = 0; i < 4; i++)
                #pragma unroll
                for (int j = 0; j < 4; j++)
                    mma16816(acc[i][j], af[i], bh[j]);
        }

        // epilogue: write ao chunk
        #pragma unroll
        for (int i = 0; i < 4; i++) {
            int r = mw + 16 * i + g;
            #pragma unroll
            for (int j = 0; j < 4; j++) {
                int c = nc * 256 + nw + 8 * j + 2 * tg;
                *(__half2*)(Cp + (size_t)r * ND + c) =
                    __floats2half2_rn(acc[i][j][0], acc[i][j][1]);
                *(__half2*)(Cp + (size_t)(r + 8) * ND + c) =
                    __floats2half2_rn(acc[i][j][2], acc[i][j][3]);
            }
        }
        __syncthreads();
    }
}

// ---------------------------------------------------------------------------
extern "C" void kernel_launch(void* const* d_in, const int* in_sizes, int n_in,
                              void* d_out, int out_size)
{
    const float* x    = (const float*)d_in[0];
    const float* ctx  = (const float*)d_in[1];
    const float* gn_w = (const float*)d_in[2];
    const float* gn_b = (const float*)d_in[3];
    const float* ln_w = (const float*)d_in[4];
    const float* ln_b = (const float*)d_in[5];
    const float* wq   = (const float*)d_in[6];
    const float* bq   = (const float*)d_in[7];
    const float* wkv  = (const float*)d_in[8];
    const float* bkv  = (const float*)d_in[9];
    const float* wo   = (const float*)d_in[10];
    const float* bo   = (const float*)d_in[11];
    float* out = (float*)d_out;

    cudaFuncSetAttribute(gemm_fp16<1>, cudaFuncAttributeMaxDynamicSharedMemorySize, GSM);
    cudaFuncSetAttribute(gemm_fp16<2>, cudaFuncAttributeMaxDynamicSharedMemorySize, GSM);
    cudaFuncSetAttribute(gemm_fp16<3>, cudaFuncAttributeMaxDynamicSharedMemorySize, GSM);
    cudaFuncSetAttribute(attn_k, cudaFuncAttributeMaxDynamicSharedMemorySize, ASM);

    h16 *xnh, *qh, *aoh, *cnh, *kh, *vh, *wqh, *wkvh, *woh;
    cudaGetSymbolAddress((void**)&xnh, g_xnh);
    cudaGetSymbolAddress((void**)&qh,  g_qh);
    cudaGetSymbolAddress((void**)&aoh, g_aoh);
    cudaGetSymbolAddress((void**)&cnh, g_cnh);
    cudaGetSymbolAddress((void**)&kh,  g_kh);
    cudaGetSymbolAddress((void**)&vh,  g_vh);
    cudaGetSymbolAddress((void**)&wqh, g_wqh);
    cudaGetSymbolAddress((void**)&wkvh, g_wkvh);
    cudaGetSymbolAddress((void**)&woh, g_woh);

    const float qscale = 0.044194173824159216f; // 512^-0.5

    // one-time side-stream setup (first call is the uncaptured correctness run)
    static cudaStream_t s1 = nullptr;
    static cudaEvent_t eFork = nullptr, eWq = nullptr, eV = nullptr, eWo = nullptr;
    static bool sinit = false, ms = false;
    if (!sinit) {
        sinit = true;
        ms = (cudaStreamCreateWithFlags(&s1, cudaStreamNonBlocking) == cudaSuccess)
          && (cudaEventCreateWithFlags(&eFork, cudaEventDisableTiming) == cudaSuccess)
          && (cudaEventCreateWithFlags(&eWq,   cudaEventDisableTiming) == cudaSuccess)
          && (cudaEventCreateWithFlags(&eV,    cudaEventDisableTiming) == cudaSuccess)
          && (cudaEventCreateWithFlags(&eWo,   cudaEventDisableTiming) == cudaSuccess);
    }

    if (ms) {
        cudaEventRecord(eFork, 0);
        cudaStreamWaitEvent(s1, eFork, 0);

        // side stream: weight conversions + context path
        convw1_k<<<(ND * ND + 1023) / 1024, 256, 0, s1>>>(wq, wqh, ND * ND);
        cudaEventRecord(eWq, s1);
        convw1_k<<<(1024 * NCTX + 1023) / 1024, 256, 0, s1>>>(wkv, wkvh, 1024 * NCTX);
        ln_k<<<NB * NS, 256, 0, s1>>>(ctx, ln_w, ln_b);
        gemm_fp16<1><<<dim3(NS / 128, ND / 128, NB), 256, GSM, s1>>>(
            cnh, wkvh, kh, bkv, nullptr, NCTX, NCTX, NCTX, ND,
            (long)NS * NCTX, 0L, (long)NS * ND);
        gemm_fp16<2><<<dim3(ND / 128, NS / 128, NB), 256, GSM, s1>>>(
            wkvh + (size_t)512 * NCTX, cnh, vh, bkv + 512, nullptr,
            NCTX, NCTX, NCTX, NS, 0L, (long)NS * NCTX, (long)ND * NS);
        cudaEventRecord(eV, s1);
        convw1_k<<<(ND * ND + 1023) / 1024, 256, 0, s1>>>(wo, woh, ND * ND);
        cudaEventRecord(eWo, s1);

        // main stream: x path
        gn_stats_k<<<NB * 32, 256>>>(x, gn_w, gn_b);
        xn_conv_k<<<dim3(NHW / 32, ND / 32, NB), dim3(32, 8)>>>(x);
        cudaStreamWaitEvent(0, eWq, 0);
        gemm_fp16<1><<<dim3(NHW / 128, ND / 128, NB), 256, GSM>>>(
            xnh, wqh, qh, bq, nullptr, ND, ND, ND, ND,
            (long)NHW * ND, 0L, (long)NHW * ND);
        cudaStreamWaitEvent(0, eV, 0);
        attn_k<<<dim3(NHW / 128, NB), 512, ASM>>>(qh, kh, vh, qscale);
        cudaStreamWaitEvent(0, eWo, 0);
        gemm_fp16<3><<<dim3(ND / 128, NHW / 128, NB), 256, GSM>>>(
            woh, aoh, out, bo, x, ND, ND, ND, NHW,
            0L, (long)NHW * ND, (long)ND * NHW);
    } else {
        // serial fallback
        convw1_k<<<(ND * ND + 1023) / 1024, 256>>>(wq, wqh, ND * ND);
        convw1_k<<<(1024 * NCTX + 1023) / 1024, 256>>>(wkv, wkvh, 1024 * NCTX);
        convw1_k<<<(ND * ND + 1023) / 1024, 256>>>(wo, woh, ND * ND);
        gn_stats_k<<<NB * 32, 256>>>(x, gn_w, gn_b);
        ln_k<<<NB * NS, 256>>>(ctx, ln_w, ln_b);
        xn_conv_k<<<dim3(NHW / 32, ND / 32, NB), dim3(32, 8)>>>(x);
        gemm_fp16<1><<<dim3(NS / 128, ND / 128, NB), 256, GSM>>>(
            cnh, wkvh, kh, bkv, nullptr, NCTX, NCTX, NCTX, ND,
            (long)NS * NCTX, 0L, (long)NS * ND);
        gemm_fp16<2><<<dim3(ND / 128, NS / 128, NB), 256, GSM>>>(
            wkvh + (size_t)512 * NCTX, cnh, vh, bkv + 512, nullptr,
            NCTX, NCTX, NCTX, NS, 0L, (long)NS * NCTX, (long)ND * NS);
        gemm_fp16<1><<<dim3(NHW / 128, ND / 128, NB), 256, GSM>>>(
            xnh, wqh, qh, bq, nullptr, ND, ND, ND, ND,
            (long)NHW * ND, 0L, (long)NHW * ND);
        attn_k<<<dim3(NHW / 128, NB), 512, ASM>>>(qh, kh, vh, qscale);
        gemm_fp16<3><<<dim3(ND / 128, NHW / 128, NB), 256, GSM>>>(
            woh, aoh, out, bo, x, ND, ND, ND, NHW,
            0L, (long)NHW * ND, (long)ND * NHW);
    }
}